// round 1
// baseline (speedup 1.0000x reference)
#include <cuda_runtime.h>

#define KK9 9
#define NJ  18
#define Bn  8
#define Cn  128
#define Hn  64
#define Wn  64
#define On  128

// scratch (no allocations allowed)
__device__ float g_off[Bn * NJ * Hn * Wn];   // offsets [b][j][h][w], j = 2*kk + d (d=0:y,1:x)
__device__ float g_wT[KK9 * Cn * On];        // w_def transposed -> [kk][c][o]

// ---------------------------------------------------------------------------
// Kernel 0: transpose w_def [O,C,3,3] -> g_wT[kk][c][o]
// ---------------------------------------------------------------------------
__global__ void wt_kernel(const float* __restrict__ w_def) {
    int idx = blockIdx.x * 256 + threadIdx.x;
    if (idx >= On * Cn * KK9) return;
    int kk = idx % KK9;
    int c  = (idx / KK9) % Cn;
    int o  = idx / (KK9 * Cn);
    g_wT[(kk * Cn + c) * On + o] = w_def[idx];
}

// ---------------------------------------------------------------------------
// Kernel 1: offset conv (3x3, pad 1, stride 1): x[8,128,64,64] -> g_off[8,18,64,64]
// One thread per output pixel, 18 accumulators; w_off chunked through smem.
// ---------------------------------------------------------------------------
__global__ __launch_bounds__(256) void off_kernel(const float* __restrict__ x,
                                                  const float* __restrict__ w_off,
                                                  const float* __restrict__ b_off) {
    // layout: wch[c_loc][j][12] (padded to 12 floats for aligned float4 loads)
    __shared__ float wch[32 * NJ * 12];

    int pix = blockIdx.x * 256 + threadIdx.x;
    int w = pix & 63;
    int h = (pix >> 6) & 63;
    int b = pix >> 12;

    float acc[NJ];
#pragma unroll
    for (int j = 0; j < NJ; j++) acc[j] = b_off[j];

    for (int cc = 0; cc < Cn; cc += 32) {
        __syncthreads();
        for (int i = threadIdx.x; i < 32 * NJ * 9; i += 256) {
            int q  = i % 9;
            int j  = (i / 9) % NJ;
            int cl = i / (9 * NJ);
            wch[(cl * NJ + j) * 12 + q] = w_off[(j * Cn + cc + cl) * 9 + q];
        }
        __syncthreads();

        for (int cl = 0; cl < 32; cl++) {
            const float* xb = x + ((b * Cn + cc + cl) * Hn) * Wn;
            float xv[9];
#pragma unroll
            for (int ky = 0; ky < 3; ky++)
#pragma unroll
                for (int kx = 0; kx < 3; kx++) {
                    int y = h - 1 + ky, xx = w - 1 + kx;
                    bool v = (y >= 0) & (y < Hn) & (xx >= 0) & (xx < Wn);
                    xv[ky * 3 + kx] = v ? xb[y * Wn + xx] : 0.0f;
                }
#pragma unroll
            for (int j = 0; j < NJ; j++) {
                const float* wp = &wch[(cl * NJ + j) * 12];
                float4 w0 = *(const float4*)wp;
                float4 w1 = *(const float4*)(wp + 4);
                float  w8 = wp[8];
                acc[j] += xv[0] * w0.x + xv[1] * w0.y + xv[2] * w0.z + xv[3] * w0.w
                        + xv[4] * w1.x + xv[5] * w1.y + xv[6] * w1.z + xv[7] * w1.w
                        + xv[8] * w8;
            }
        }
    }

#pragma unroll
    for (int j = 0; j < NJ; j++)
        g_off[((b * NJ + j) * Hn + h) * Wn + w] = acc[j];
}

// ---------------------------------------------------------------------------
// Kernel 2: fused bilinear sample + contraction.
// Block = 128 threads, handles 32 pixels (b, h, w0..w0+31) x 128 output chans.
// Per kk: gather sampled tile S[c][p] into smem, then thread-o GEMM with
// acc[32] pixel accumulators.
// ---------------------------------------------------------------------------
__global__ __launch_bounds__(128) void main_kernel(const float* __restrict__ x,
                                                   const float* __restrict__ b_def,
                                                   float* __restrict__ out) {
    __shared__ float S[Cn * 36];            // sampled tile, stride 36 (conflict-free + 16B aligned)
    __shared__ int   s_iy0[32 * KK9];
    __shared__ int   s_ix0[32 * KK9];
    __shared__ float s_wy[32 * KK9];
    __shared__ float s_wx[32 * KK9];

    int blk = blockIdx.x;
    int b   = blk >> 7;                     // 128 blocks per batch
    int rem = blk & 127;
    int h   = rem >> 1;
    int w0  = (rem & 1) * 32;
    int tid = threadIdx.x;

    // ---- Phase A: sampling metadata for all (pixel, kk) pairs ----
    for (int i = tid; i < 32 * KK9; i += 128) {
        int p  = i / KK9, kk = i % KK9;
        int ky = kk / 3,  kx = kk % 3;
        float offy = g_off[((b * NJ + 2 * kk)     * Hn + h) * Wn + w0 + p];
        float offx = g_off[((b * NJ + 2 * kk + 1) * Hn + h) * Wn + w0 + p];
        float py = (float)(h - 1 + ky) + offy;
        float px = (float)(w0 + p - 1 + kx) + offx;
        float fy = floorf(py), fx = floorf(px);
        s_iy0[i] = (int)fy;
        s_ix0[i] = (int)fx;
        s_wy[i]  = py - fy;
        s_wx[i]  = px - fx;
    }
    __syncthreads();

    float acc[32];
    float bd = b_def[tid];
#pragma unroll
    for (int p = 0; p < 32; p++) acc[p] = bd;

    int lane = tid & 31;   // pixel index in phase B
    int wid  = tid >> 5;   // channel group in phase B

    for (int kk = 0; kk < KK9; kk++) {
        // ---- Phase B: bilinear gather of 128 channels x 32 pixels ----
        int m = lane * KK9 + kk;             // stride-9 smem reads: conflict-free
        int iy0 = s_iy0[m], ix0 = s_ix0[m];
        float wy = s_wy[m], wx = s_wx[m];
        float w00 = (1.f - wy) * (1.f - wx);
        float w01 = (1.f - wy) * wx;
        float w10 = wy * (1.f - wx);
        float w11 = wy * wx;
        int iy1 = iy0 + 1, ix1 = ix0 + 1;
        bool vy0 = (iy0 >= 0) & (iy0 < Hn), vy1 = (iy1 >= 0) & (iy1 < Hn);
        bool vx0 = (ix0 >= 0) & (ix0 < Wn), vx1 = (ix1 >= 0) & (ix1 < Wn);
        bool v00 = vy0 & vx0, v01 = vy0 & vx1, v10 = vy1 & vx0, v11 = vy1 & vx1;
        int o00 = iy0 * Wn + ix0, o01 = iy0 * Wn + ix1;
        int o10 = iy1 * Wn + ix0, o11 = iy1 * Wn + ix1;

        const float* xb = x + (size_t)(b * Cn + wid * 32) * Hn * Wn;
#pragma unroll 4
        for (int ci = 0; ci < 32; ci++) {
            const float* xc = xb + ci * Hn * Wn;
            float a00 = v00 ? xc[o00] : 0.0f;
            float a01 = v01 ? xc[o01] : 0.0f;
            float a10 = v10 ? xc[o10] : 0.0f;
            float a11 = v11 ? xc[o11] : 0.0f;
            S[(wid * 32 + ci) * 36 + lane] = a00 * w00 + a01 * w01 + a10 * w10 + a11 * w11;
        }
        __syncthreads();

        // ---- Phase C: rank-1 updates; thread = output channel o = tid ----
        const float* wp = g_wT + kk * Cn * On + tid;   // coalesced across o
#pragma unroll 2
        for (int c = 0; c < Cn; c++) {
            float wv = wp[c * On];
            const float4* sp = (const float4*)&S[c * 36];
#pragma unroll
            for (int q = 0; q < 8; q++) {
                float4 v = sp[q];
                acc[q * 4 + 0] += v.x * wv;
                acc[q * 4 + 1] += v.y * wv;
                acc[q * 4 + 2] += v.z * wv;
                acc[q * 4 + 3] += v.w * wv;
            }
        }
        __syncthreads();
    }

    // ---- Epilogue: transpose through smem for coalesced global stores ----
#pragma unroll
    for (int p = 0; p < 32; p++) S[tid * 36 + p] = acc[p];
    __syncthreads();

    float* ob = out + (size_t)(b * On) * Hn * Wn + h * Wn + w0;
    for (int i = tid; i < 128 * 32; i += 128) {
        int o = i >> 5, p = i & 31;
        ob[(size_t)o * Hn * Wn + p] = S[o * 36 + p];
    }
}

// ---------------------------------------------------------------------------
extern "C" void kernel_launch(void* const* d_in, const int* in_sizes, int n_in,
                              void* d_out, int out_size) {
    const float* x     = (const float*)d_in[0];
    const float* w_off = (const float*)d_in[1];
    const float* b_off = (const float*)d_in[2];
    const float* w_def = (const float*)d_in[3];
    const float* b_def = (const float*)d_in[4];
    float* out = (float*)d_out;

    wt_kernel<<<(On * Cn * KK9 + 255) / 256, 256>>>(w_def);
    off_kernel<<<(Bn * Hn * Wn) / 256, 256>>>(x, w_off, b_off);
    main_kernel<<<Bn * Hn * (Wn / 32), 128>>>(x, b_def, out);
}

// round 2
// speedup vs baseline: 1.3346x; 1.3346x over previous
#include <cuda_runtime.h>

#define KK9 9
#define NJ  18
#define Bn  8
#define Cn  128
#define Hn  64
#define Wn  64
#define On  128

// scratch (no allocations allowed)
__device__ float g_off[Bn * NJ * Hn * Wn];   // offsets [b][j][h][w], j = 2*kk + d (d=0:y,1:x)
__device__ float g_wT[KK9 * Cn * On];        // w_def transposed -> [kk][c][o]

// ---- packed f32x2 helpers (sm_103a FFMA2 — ptxas won't auto-fuse) ----------
__device__ __forceinline__ unsigned long long pack2(float a, float b) {
    unsigned long long r;
    asm("mov.b64 %0, {%1, %2};" : "=l"(r) : "f"(a), "f"(b));
    return r;
}
__device__ __forceinline__ unsigned long long ffma2(unsigned long long a,
                                                    unsigned long long b,
                                                    unsigned long long c) {
    unsigned long long d;
    asm("fma.rn.f32x2 %0, %1, %2, %3;" : "=l"(d) : "l"(a), "l"(b), "l"(c));
    return d;
}
__device__ __forceinline__ void unpack2(unsigned long long v, float& lo, float& hi) {
    asm("mov.b64 {%0, %1}, %2;" : "=f"(lo), "=f"(hi) : "l"(v));
}

// ---------------------------------------------------------------------------
// Kernel 0: transpose w_def [O,C,3,3] -> g_wT[kk][c][o]
// ---------------------------------------------------------------------------
__global__ void wt_kernel(const float* __restrict__ w_def) {
    int idx = blockIdx.x * 256 + threadIdx.x;
    if (idx >= On * Cn * KK9) return;
    int kk = idx % KK9;
    int c  = (idx / KK9) % Cn;
    int o  = idx / (KK9 * Cn);
    g_wT[(kk * Cn + c) * On + o] = w_def[idx];
}

// ---------------------------------------------------------------------------
// Kernel 1: offset conv (3x3, pad 1, stride 1): x[8,128,64,64] -> g_off[8,18,64,64]
// ---------------------------------------------------------------------------
__global__ __launch_bounds__(256) void off_kernel(const float* __restrict__ x,
                                                  const float* __restrict__ w_off,
                                                  const float* __restrict__ b_off) {
    __shared__ float wch[32 * NJ * 12];      // [c_loc][j][12] padded for float4

    int pix = blockIdx.x * 256 + threadIdx.x;
    int w = pix & 63;
    int h = (pix >> 6) & 63;
    int b = pix >> 12;

    float acc[NJ];
#pragma unroll
    for (int j = 0; j < NJ; j++) acc[j] = b_off[j];

    for (int cc = 0; cc < Cn; cc += 32) {
        __syncthreads();
        for (int i = threadIdx.x; i < 32 * NJ * 9; i += 256) {
            int q  = i % 9;
            int j  = (i / 9) % NJ;
            int cl = i / (9 * NJ);
            wch[(cl * NJ + j) * 12 + q] = w_off[(j * Cn + cc + cl) * 9 + q];
        }
        __syncthreads();

        for (int cl = 0; cl < 32; cl++) {
            const float* xb = x + ((b * Cn + cc + cl) * Hn) * Wn;
            float xv[9];
#pragma unroll
            for (int ky = 0; ky < 3; ky++)
#pragma unroll
                for (int kx = 0; kx < 3; kx++) {
                    int y = h - 1 + ky, xx = w - 1 + kx;
                    bool v = (y >= 0) & (y < Hn) & (xx >= 0) & (xx < Wn);
                    xv[ky * 3 + kx] = v ? xb[y * Wn + xx] : 0.0f;
                }
#pragma unroll
            for (int j = 0; j < NJ; j++) {
                const float* wp = &wch[(cl * NJ + j) * 12];
                float4 w0 = *(const float4*)wp;
                float4 w1 = *(const float4*)(wp + 4);
                float  w8 = wp[8];
                acc[j] += xv[0] * w0.x + xv[1] * w0.y + xv[2] * w0.z + xv[3] * w0.w
                        + xv[4] * w1.x + xv[5] * w1.y + xv[6] * w1.z + xv[7] * w1.w
                        + xv[8] * w8;
            }
        }
    }

#pragma unroll
    for (int j = 0; j < NJ; j++)
        g_off[((b * NJ + j) * Hn + h) * Wn + w] = acc[j];
}

// ---------------------------------------------------------------------------
// Kernel 2: fused bilinear sample + contraction (FFMA2 phase C).
// Block = 128 threads, 32 pixels x 128 output channels.
// ---------------------------------------------------------------------------
__global__ __launch_bounds__(128) void main_kernel(const float* __restrict__ x,
                                                   const float* __restrict__ b_def,
                                                   float* __restrict__ out) {
    __shared__ float S[Cn * 36];            // sampled tile, stride 36 (conflict-free, 16B aligned)
    __shared__ int   s_iy0[32 * KK9];
    __shared__ int   s_ix0[32 * KK9];
    __shared__ float s_wy[32 * KK9];
    __shared__ float s_wx[32 * KK9];

    int blk = blockIdx.x;
    int b   = blk >> 7;
    int rem = blk & 127;
    int h   = rem >> 1;
    int w0  = (rem & 1) * 32;
    int tid = threadIdx.x;

    // ---- Phase A: sampling metadata ----
    for (int i = tid; i < 32 * KK9; i += 128) {
        int p  = i / KK9, kk = i % KK9;
        int ky = kk / 3,  kx = kk % 3;
        float offy = g_off[((b * NJ + 2 * kk)     * Hn + h) * Wn + w0 + p];
        float offx = g_off[((b * NJ + 2 * kk + 1) * Hn + h) * Wn + w0 + p];
        float py = (float)(h - 1 + ky) + offy;
        float px = (float)(w0 + p - 1 + kx) + offx;
        float fy = floorf(py), fx = floorf(px);
        s_iy0[i] = (int)fy;
        s_ix0[i] = (int)fx;
        s_wy[i]  = py - fy;
        s_wx[i]  = px - fx;
    }
    __syncthreads();

    // ---- packed accumulators: 16 x f32x2 covering 32 pixels ----
    unsigned long long acc2[16];
    {
        float bd = b_def[tid];
        unsigned long long bd2 = pack2(bd, bd);
#pragma unroll
        for (int q = 0; q < 16; q++) acc2[q] = bd2;
    }

    int lane = tid & 31;   // pixel index in phase B
    int wid  = tid >> 5;   // channel group in phase B

    for (int kk = 0; kk < KK9; kk++) {
        // ---- Phase B: bilinear gather, 128 channels x 32 pixels ----
        int m = lane * KK9 + kk;
        int iy0 = s_iy0[m], ix0 = s_ix0[m];
        float wy = s_wy[m], wx = s_wx[m];
        float w00 = (1.f - wy) * (1.f - wx);
        float w01 = (1.f - wy) * wx;
        float w10 = wy * (1.f - wx);
        float w11 = wy * wx;
        int iy1 = iy0 + 1, ix1 = ix0 + 1;
        bool vy0 = (iy0 >= 0) & (iy0 < Hn), vy1 = (iy1 >= 0) & (iy1 < Hn);
        bool vx0 = (ix0 >= 0) & (ix0 < Wn), vx1 = (ix1 >= 0) & (ix1 < Wn);
        bool v00 = vy0 & vx0, v01 = vy0 & vx1, v10 = vy1 & vx0, v11 = vy1 & vx1;
        int o00 = iy0 * Wn + ix0, o01 = iy0 * Wn + ix1;
        int o10 = iy1 * Wn + ix0, o11 = iy1 * Wn + ix1;

        const float* xb = x + (size_t)(b * Cn + wid * 32) * Hn * Wn;
#pragma unroll 4
        for (int ci = 0; ci < 32; ci++) {
            const float* xc = xb + ci * Hn * Wn;
            float a00 = v00 ? xc[o00] : 0.0f;
            float a01 = v01 ? xc[o01] : 0.0f;
            float a10 = v10 ? xc[o10] : 0.0f;
            float a11 = v11 ? xc[o11] : 0.0f;
            S[(wid * 32 + ci) * 36 + lane] = a00 * w00 + a01 * w01 + a10 * w10 + a11 * w11;
        }
        __syncthreads();

        // ---- Phase C: rank-1 updates with packed FFMA2; thread = o = tid ----
        const float* wp = g_wT + kk * Cn * On + tid;   // coalesced across o
#pragma unroll 4
        for (int c = 0; c < Cn; c++) {
            float wv = wp[c * On];
            unsigned long long wv2 = pack2(wv, wv);
            const ulonglong2* sp = (const ulonglong2*)&S[c * 36];
#pragma unroll
            for (int q = 0; q < 8; q++) {
                ulonglong2 v = sp[q];               // LDS.128: two f32x2 lanes
                acc2[2 * q]     = ffma2(v.x, wv2, acc2[2 * q]);
                acc2[2 * q + 1] = ffma2(v.y, wv2, acc2[2 * q + 1]);
            }
        }
        __syncthreads();
    }

    // ---- Epilogue: unpack + transpose through smem for coalesced stores ----
#pragma unroll
    for (int q = 0; q < 16; q++) {
        float lo, hi;
        unpack2(acc2[q], lo, hi);
        S[tid * 36 + 2 * q]     = lo;
        S[tid * 36 + 2 * q + 1] = hi;
    }
    __syncthreads();

    float* ob = out + (size_t)(b * On) * Hn * Wn + h * Wn + w0;
    for (int i = tid; i < 128 * 32; i += 128) {
        int o = i >> 5, p = i & 31;
        ob[(size_t)o * Hn * Wn + p] = S[o * 36 + p];
    }
}

// ---------------------------------------------------------------------------
extern "C" void kernel_launch(void* const* d_in, const int* in_sizes, int n_in,
                              void* d_out, int out_size) {
    const float* x     = (const float*)d_in[0];
    const float* w_off = (const float*)d_in[1];
    const float* b_off = (const float*)d_in[2];
    const float* w_def = (const float*)d_in[3];
    const float* b_def = (const float*)d_in[4];
    float* out = (float*)d_out;

    wt_kernel<<<(On * Cn * KK9 + 255) / 256, 256>>>(w_def);
    off_kernel<<<(Bn * Hn * Wn) / 256, 256>>>(x, w_off, b_off);
    main_kernel<<<Bn * Hn * (Wn / 32), 128>>>(x, b_def, out);
}

// round 3
// speedup vs baseline: 1.3427x; 1.0061x over previous
#include <cuda_runtime.h>

#define KK9 9
#define NJ  18
#define Bn  8
#define Cn  128
#define Hn  64
#define Wn  64
#define On  128

// scratch (no allocations allowed)
__device__ float g_off[Bn * NJ * Hn * Wn];   // offsets [b][j][h][w], j = 2*kk + d
__device__ float g_wT[KK9 * Cn * On];        // w_def transposed -> [kk][c][o]

// ---- packed f32x2 helpers ---------------------------------------------------
typedef unsigned long long u64t;
__device__ __forceinline__ u64t pack2(float a, float b) {
    u64t r; asm("mov.b64 %0, {%1, %2};" : "=l"(r) : "f"(a), "f"(b)); return r;
}
__device__ __forceinline__ u64t ffma2(u64t a, u64t b, u64t c) {
    u64t d; asm("fma.rn.f32x2 %0, %1, %2, %3;" : "=l"(d) : "l"(a), "l"(b), "l"(c)); return d;
}
__device__ __forceinline__ void unpack2(u64t v, float& lo, float& hi) {
    asm("mov.b64 {%0, %1}, %2;" : "=f"(lo), "=f"(hi) : "l"(v));
}

// ---------------------------------------------------------------------------
// Kernel 1: offset conv (+ fused w_def transpose at the top, independent work)
// ---------------------------------------------------------------------------
__global__ __launch_bounds__(256) void off_kernel(const float* __restrict__ x,
                                                  const float* __restrict__ w_off,
                                                  const float* __restrict__ b_off,
                                                  const float* __restrict__ w_def) {
    // ---- fused transpose: w_def [O,C,3,3] -> g_wT[kk][c][o] ----
    {
        int gt = blockIdx.x * 256 + threadIdx.x;          // 32768 threads total
        for (int idx = gt; idx < On * Cn * KK9; idx += Bn * Hn * Wn) {
            int kk = idx % KK9;
            int c  = (idx / KK9) % Cn;
            int o  = idx / (KK9 * Cn);
            g_wT[(kk * Cn + c) * On + o] = w_def[idx];
        }
    }

    __shared__ float wch[32 * NJ * 12];      // [c_loc][j][12] padded for float4

    int pix = blockIdx.x * 256 + threadIdx.x;
    int w = pix & 63;
    int h = (pix >> 6) & 63;
    int b = pix >> 12;

    float acc[NJ];
#pragma unroll
    for (int j = 0; j < NJ; j++) acc[j] = b_off[j];

    for (int cc = 0; cc < Cn; cc += 32) {
        __syncthreads();
        for (int i = threadIdx.x; i < 32 * NJ * 9; i += 256) {
            int q  = i % 9;
            int j  = (i / 9) % NJ;
            int cl = i / (9 * NJ);
            wch[(cl * NJ + j) * 12 + q] = w_off[(j * Cn + cc + cl) * 9 + q];
        }
        __syncthreads();

        for (int cl = 0; cl < 32; cl++) {
            const float* xb = x + ((b * Cn + cc + cl) * Hn) * Wn;
            float xv[9];
#pragma unroll
            for (int ky = 0; ky < 3; ky++)
#pragma unroll
                for (int kx = 0; kx < 3; kx++) {
                    int y = h - 1 + ky, xx = w - 1 + kx;
                    bool v = (y >= 0) & (y < Hn) & (xx >= 0) & (xx < Wn);
                    xv[ky * 3 + kx] = v ? xb[y * Wn + xx] : 0.0f;
                }
#pragma unroll
            for (int j = 0; j < NJ; j++) {
                const float* wp = &wch[(cl * NJ + j) * 12];
                float4 w0 = *(const float4*)wp;
                float4 w1 = *(const float4*)(wp + 4);
                float  w8 = wp[8];
                acc[j] += xv[0] * w0.x + xv[1] * w0.y + xv[2] * w0.z + xv[3] * w0.w
                        + xv[4] * w1.x + xv[5] * w1.y + xv[6] * w1.z + xv[7] * w1.w
                        + xv[8] * w8;
            }
        }
    }

#pragma unroll
    for (int j = 0; j < NJ; j++)
        g_off[((b * NJ + j) * Hn + h) * Wn + w] = acc[j];
}

// ---------------------------------------------------------------------------
// Kernel 2: fused bilinear sample + contraction, 2D register tiling.
// Block = 256 threads, tile = 128 o x 64 pixels (one full output row).
// Thread tile = 8 o x 4 p, accumulators paired over o (f32x2).
// ---------------------------------------------------------------------------
__global__ __launch_bounds__(256) void main_kernel(const float* __restrict__ x,
                                                   const float* __restrict__ b_def,
                                                   float* __restrict__ out) {
    __shared__ float S[Cn * 68];             // 34.8 KB sampled tile / epilogue staging
    __shared__ int   s_iy0[64 * KK9];
    __shared__ int   s_ix0[64 * KK9];
    __shared__ float s_wy[64 * KK9];
    __shared__ float s_wx[64 * KK9];

    int b = blockIdx.x >> 6;                 // 64 blocks per batch (one per row h)
    int h = blockIdx.x & 63;
    int tid = threadIdx.x;

    // ---- Phase A: sampling metadata for 64 pixels x 9 kk ----
    for (int i = tid; i < 64 * KK9; i += 256) {
        int p  = i / KK9, kk = i % KK9;
        int ky = kk / 3,  kx = kk % 3;
        float offy = g_off[((b * NJ + 2 * kk)     * Hn + h) * Wn + p];
        float offx = g_off[((b * NJ + 2 * kk + 1) * Hn + h) * Wn + p];
        float py = (float)(h - 1 + ky) + offy;
        float px = (float)(p - 1 + kx) + offx;
        float fy = floorf(py), fx = floorf(px);
        s_iy0[i] = (int)fy;
        s_ix0[i] = (int)fx;
        s_wy[i]  = py - fy;
        s_wx[i]  = px - fx;
    }
    __syncthreads();

    // ---- accumulators: 16 f32x2 = 8 o x 4 p, paired over o ----
    int oq = tid >> 4;                       // 0..15 -> o0 = oq*8
    int pq = tid & 15;                       // 0..15 -> p0 = pq*4
    int o0 = oq * 8;
    int p0 = pq * 4;

    u64t acc2[16];
#pragma unroll
    for (int op = 0; op < 4; op++) {
        float2 bd = *(const float2*)(b_def + o0 + 2 * op);
        u64t bd2 = pack2(bd.x, bd.y);
#pragma unroll
        for (int pp = 0; pp < 4; pp++) acc2[op * 4 + pp] = bd2;
    }

    // phase-B mapping: 8 warps; warp covers (32-pixel half) x (32-channel group)
    int lane = tid & 31;
    int wrp  = tid >> 5;
    int pB   = (wrp & 1) * 32 + lane;        // pixel this thread gathers
    int cg   = wrp >> 1;                     // channel group (0..3)

    for (int kk = 0; kk < KK9; kk++) {
        // ---- Phase B: bilinear gather 128c x 64p ----
        {
            int m = pB * KK9 + kk;
            int iy0 = s_iy0[m], ix0 = s_ix0[m];
            float wy = s_wy[m], wx = s_wx[m];
            float w00 = (1.f - wy) * (1.f - wx);
            float w01 = (1.f - wy) * wx;
            float w10 = wy * (1.f - wx);
            float w11 = wy * wx;
            int iy1 = iy0 + 1, ix1 = ix0 + 1;
            bool vy0 = (iy0 >= 0) & (iy0 < Hn), vy1 = (iy1 >= 0) & (iy1 < Hn);
            bool vx0 = (ix0 >= 0) & (ix0 < Wn), vx1 = (ix1 >= 0) & (ix1 < Wn);
            bool v00 = vy0 & vx0, v01 = vy0 & vx1, v10 = vy1 & vx0, v11 = vy1 & vx1;
            int o00 = iy0 * Wn + ix0, o01 = iy0 * Wn + ix1;
            int o10 = iy1 * Wn + ix0, o11 = iy1 * Wn + ix1;

            const float* xb = x + (size_t)(b * Cn + cg * 32) * Hn * Wn;
#pragma unroll 4
            for (int ci = 0; ci < 32; ci++) {
                const float* xc = xb + ci * Hn * Wn;
                float a00 = v00 ? xc[o00] : 0.0f;
                float a01 = v01 ? xc[o01] : 0.0f;
                float a10 = v10 ? xc[o10] : 0.0f;
                float a11 = v11 ? xc[o11] : 0.0f;
                S[(cg * 32 + ci) * 68 + pB] = a00 * w00 + a01 * w01 + a10 * w10 + a11 * w11;
            }
        }
        __syncthreads();

        // ---- Phase C: register-tiled rank-1 updates ----
        const float* wp = g_wT + kk * Cn * On + o0;   // [c][o], 8 floats per thread per c
        const float* sp = S + p0;
#pragma unroll 2
        for (int c = 0; c < Cn; c++) {
            const ulonglong2* w2 = (const ulonglong2*)(wp + c * On);
            ulonglong2 wa = w2[0];             // (o0,o0+1),(o0+2,o0+3)
            ulonglong2 wb = w2[1];             // (o0+4,o0+5),(o0+6,o0+7)
            float4 sv = *(const float4*)(sp + c * 68);
            u64t s0 = pack2(sv.x, sv.x);
            u64t s1 = pack2(sv.y, sv.y);
            u64t s2 = pack2(sv.z, sv.z);
            u64t s3 = pack2(sv.w, sv.w);

            acc2[0]  = ffma2(wa.x, s0, acc2[0]);
            acc2[1]  = ffma2(wa.x, s1, acc2[1]);
            acc2[2]  = ffma2(wa.x, s2, acc2[2]);
            acc2[3]  = ffma2(wa.x, s3, acc2[3]);
            acc2[4]  = ffma2(wa.y, s0, acc2[4]);
            acc2[5]  = ffma2(wa.y, s1, acc2[5]);
            acc2[6]  = ffma2(wa.y, s2, acc2[6]);
            acc2[7]  = ffma2(wa.y, s3, acc2[7]);
            acc2[8]  = ffma2(wb.x, s0, acc2[8]);
            acc2[9]  = ffma2(wb.x, s1, acc2[9]);
            acc2[10] = ffma2(wb.x, s2, acc2[10]);
            acc2[11] = ffma2(wb.x, s3, acc2[11]);
            acc2[12] = ffma2(wb.y, s0, acc2[12]);
            acc2[13] = ffma2(wb.y, s1, acc2[13]);
            acc2[14] = ffma2(wb.y, s2, acc2[14]);
            acc2[15] = ffma2(wb.y, s3, acc2[15]);
        }
        __syncthreads();                       // S reused by next kk's gather
    }

    // ---- Epilogue: unpack into smem, then coalesced stores ----
#pragma unroll
    for (int op = 0; op < 4; op++)
#pragma unroll
        for (int pp = 0; pp < 4; pp++) {
            float lo, hi;
            unpack2(acc2[op * 4 + pp], lo, hi);
            S[(o0 + 2 * op)     * 68 + p0 + pp] = lo;
            S[(o0 + 2 * op + 1) * 68 + p0 + pp] = hi;
        }
    __syncthreads();

    float* ob = out + ((size_t)(b * On) * Hn + h) * Wn;
    for (int i = tid; i < On * 64; i += 256) {
        int o = i >> 6, p = i & 63;
        ob[(size_t)o * Hn * Wn + p] = S[o * 68 + p];
    }
}

// ---------------------------------------------------------------------------
extern "C" void kernel_launch(void* const* d_in, const int* in_sizes, int n_in,
                              void* d_out, int out_size) {
    const float* x     = (const float*)d_in[0];
    const float* w_off = (const float*)d_in[1];
    const float* b_off = (const float*)d_in[2];
    const float* w_def = (const float*)d_in[3];
    const float* b_def = (const float*)d_in[4];
    float* out = (float*)d_out;

    off_kernel<<<(Bn * Hn * Wn) / 256, 256>>>(x, w_off, b_off, w_def);
    main_kernel<<<Bn * Hn, 256>>>(x, b_def, out);
}

// round 4
// speedup vs baseline: 1.5538x; 1.1572x over previous
#include <cuda_runtime.h>

#define KK9 9
#define NJ  18
#define Bn  8
#define Cn  128
#define Hn  64
#define Wn  64
#define On  128
#define NCHUNK 4

// scratch (no allocations allowed)
__device__ float g_off_part[NCHUNK * Bn * NJ * Hn * Wn];  // partial offsets per c-chunk
__device__ float g_wT[KK9 * Cn * On];                     // w_def -> [kk][c][o]

// ---- packed f32x2 helpers ---------------------------------------------------
typedef unsigned long long u64t;
__device__ __forceinline__ u64t pack2(float a, float b) {
    u64t r; asm("mov.b64 %0, {%1, %2};" : "=l"(r) : "f"(a), "f"(b)); return r;
}
__device__ __forceinline__ u64t ffma2(u64t a, u64t b, u64t c) {
    u64t d; asm("fma.rn.f32x2 %0, %1, %2, %3;" : "=l"(d) : "l"(a), "l"(b), "l"(c)); return d;
}
__device__ __forceinline__ void unpack2(u64t v, float& lo, float& hi) {
    asm("mov.b64 {%0, %1}, %2;" : "=f"(lo), "=f"(hi) : "l"(v));
}

// ---------------------------------------------------------------------------
// Kernel 1: offset conv partials over a 32-channel chunk (+ fused w_def
// transpose). grid = 512 (128 pixel-blocks x 4 chunks), 256 threads.
// FFMA2 over j-pairs with u64-packed weights in smem.
// ---------------------------------------------------------------------------
__global__ __launch_bounds__(256) void off_kernel(const float* __restrict__ x,
                                                  const float* __restrict__ w_off,
                                                  const float* __restrict__ b_off,
                                                  const float* __restrict__ w_def) {
    // fused transpose: w_def [O,C,3,3] -> g_wT[kk][c][o]  (spread over all 512 blocks)
    {
        int gt = blockIdx.x * 256 + threadIdx.x;
        for (int idx = gt; idx < On * Cn * KK9; idx += 512 * 256) {
            int kk = idx % KK9;
            int c  = (idx / KK9) % Cn;
            int o  = idx / (KK9 * Cn);
            g_wT[(kk * Cn + c) * On + o] = w_def[idx];
        }
    }

    // packed weights: wch2[cl][jp][10] u64  (u64 = {w[2jp], w[2jp+1]} at (c,q))
    __shared__ u64t wch2[32 * KK9 * 10];

    int chunk = blockIdx.x >> 7;             // 0..3 -> channels [chunk*32, +32)
    int pixblk = blockIdx.x & 127;
    int cc = chunk * 32;

    int pix = pixblk * 256 + threadIdx.x;
    int w = pix & 63;
    int h = (pix >> 6) & 63;
    int b = pix >> 12;

    for (int i = threadIdx.x; i < 32 * KK9 * 9; i += 256) {
        int q  = i % 9;
        int jp = (i / 9) % KK9;
        int cl = i / (9 * KK9);
        float lo = w_off[((2 * jp)     * Cn + cc + cl) * 9 + q];
        float hi = w_off[((2 * jp + 1) * Cn + cc + cl) * 9 + q];
        wch2[(cl * KK9 + jp) * 10 + q] = pack2(lo, hi);
    }
    __syncthreads();

    u64t acc2[KK9];
#pragma unroll
    for (int jp = 0; jp < KK9; jp++)
        acc2[jp] = (chunk == 0) ? pack2(b_off[2 * jp], b_off[2 * jp + 1]) : 0ULL;

    for (int cl = 0; cl < 32; cl++) {
        const float* xb = x + ((b * Cn + cc + cl) * Hn) * Wn;
        u64t x2[9];
#pragma unroll
        for (int ky = 0; ky < 3; ky++)
#pragma unroll
            for (int kx = 0; kx < 3; kx++) {
                int y = h - 1 + ky, xx = w - 1 + kx;
                bool v = (y >= 0) & (y < Hn) & (xx >= 0) & (xx < Wn);
                float xv = v ? xb[y * Wn + xx] : 0.0f;
                x2[ky * 3 + kx] = pack2(xv, xv);
            }
#pragma unroll
        for (int jp = 0; jp < KK9; jp++) {
            const u64t* wp = &wch2[(cl * KK9 + jp) * 10];
            ulonglong2 w01 = *(const ulonglong2*)(wp);
            ulonglong2 w23 = *(const ulonglong2*)(wp + 2);
            ulonglong2 w45 = *(const ulonglong2*)(wp + 4);
            ulonglong2 w67 = *(const ulonglong2*)(wp + 6);
            u64t       w8  = wp[8];
            u64t a = acc2[jp];
            a = ffma2(w01.x, x2[0], a);
            a = ffma2(w01.y, x2[1], a);
            a = ffma2(w23.x, x2[2], a);
            a = ffma2(w23.y, x2[3], a);
            a = ffma2(w45.x, x2[4], a);
            a = ffma2(w45.y, x2[5], a);
            a = ffma2(w67.x, x2[6], a);
            a = ffma2(w67.y, x2[7], a);
            a = ffma2(w8,    x2[8], a);
            acc2[jp] = a;
        }
    }

    float* op = g_off_part + (size_t)chunk * Bn * NJ * Hn * Wn;
#pragma unroll
    for (int jp = 0; jp < KK9; jp++) {
        float lo, hi;
        unpack2(acc2[jp], lo, hi);
        op[((b * NJ + 2 * jp)     * Hn + h) * Wn + w] = lo;
        op[((b * NJ + 2 * jp + 1) * Hn + h) * Wn + w] = hi;
    }
}

// ---------------------------------------------------------------------------
// Kernel 2: fused bilinear sample + contraction.
// Block = 128 threads, tile = 128 o x 64 p (one row), thread tile 8o x 8p.
// Accumulators paired over o (f32x2); 4 blocks/SM.
// ---------------------------------------------------------------------------
__global__ __launch_bounds__(128, 4) void main_kernel(const float* __restrict__ x,
                                                      const float* __restrict__ b_def,
                                                      float* __restrict__ out) {
    __shared__ float S[Cn * 68];             // 34.8 KB sampled tile / staging
    __shared__ int   s_iy0[64 * KK9];
    __shared__ int   s_ix0[64 * KK9];
    __shared__ float s_wy[64 * KK9];
    __shared__ float s_wx[64 * KK9];

    int b = blockIdx.x >> 6;
    int h = blockIdx.x & 63;
    int tid = threadIdx.x;

    // ---- Phase A: sampling metadata (sum the 4 offset partials) ----
    for (int i = tid; i < 64 * KK9; i += 128) {
        int p  = i / KK9, kk = i % KK9;
        int ky = kk / 3,  kx = kk % 3;
        size_t base_y = ((size_t)(b * NJ + 2 * kk)     * Hn + h) * Wn + p;
        size_t base_x = ((size_t)(b * NJ + 2 * kk + 1) * Hn + h) * Wn + p;
        const size_t CS = (size_t)Bn * NJ * Hn * Wn;
        float offy = g_off_part[base_y] + g_off_part[CS + base_y]
                   + g_off_part[2 * CS + base_y] + g_off_part[3 * CS + base_y];
        float offx = g_off_part[base_x] + g_off_part[CS + base_x]
                   + g_off_part[2 * CS + base_x] + g_off_part[3 * CS + base_x];
        float py = (float)(h - 1 + ky) + offy;
        float px = (float)(p - 1 + kx) + offx;
        float fy = floorf(py), fx = floorf(px);
        s_iy0[i] = (int)fy;
        s_ix0[i] = (int)fx;
        s_wy[i]  = py - fy;
        s_wx[i]  = px - fx;
    }
    __syncthreads();

    // ---- accumulators: 32 f32x2 = (4 o-pairs-of-2) x 8 p = 8o x 8p ----
    int oq = tid >> 3;                       // 0..15 -> o0 = oq*8
    int pq = tid & 7;                        // 0..7  -> p0 = pq*8
    int o0 = oq * 8;
    int p0 = pq * 8;

    u64t acc2[32];
#pragma unroll
    for (int i = 0; i < 4; i++) {
        float2 bd = *(const float2*)(b_def + o0 + 2 * i);
        u64t bd2 = pack2(bd.x, bd.y);
#pragma unroll
        for (int j = 0; j < 8; j++) acc2[i * 8 + j] = bd2;
    }

    // phase-B mapping: thread = (pixel pB, channel half)
    int pB    = tid & 63;
    int cHalf = tid >> 6;                    // 0/1 -> 64 channels each

    for (int kk = 0; kk < KK9; kk++) {
        // ---- Phase B: bilinear gather 128c x 64p ----
        {
            int m = pB * KK9 + kk;
            int iy0 = s_iy0[m], ix0 = s_ix0[m];
            float wy = s_wy[m], wx = s_wx[m];
            float w00 = (1.f - wy) * (1.f - wx);
            float w01 = (1.f - wy) * wx;
            float w10 = wy * (1.f - wx);
            float w11 = wy * wx;
            int iy1 = iy0 + 1, ix1 = ix0 + 1;
            bool vy0 = (iy0 >= 0) & (iy0 < Hn), vy1 = (iy1 >= 0) & (iy1 < Hn);
            bool vx0 = (ix0 >= 0) & (ix0 < Wn), vx1 = (ix1 >= 0) & (ix1 < Wn);
            bool v00 = vy0 & vx0, v01 = vy0 & vx1, v10 = vy1 & vx0, v11 = vy1 & vx1;
            int o00 = iy0 * Wn + ix0, o01 = iy0 * Wn + ix1;
            int o10 = iy1 * Wn + ix0, o11 = iy1 * Wn + ix1;

            const float* xb = x + (size_t)(b * Cn + cHalf * 64) * Hn * Wn;
            float* srow = S + (size_t)cHalf * 64 * 68 + pB;
#pragma unroll 4
            for (int ci = 0; ci < 64; ci++) {
                const float* xc = xb + ci * Hn * Wn;
                float a00 = v00 ? xc[o00] : 0.0f;
                float a01 = v01 ? xc[o01] : 0.0f;
                float a10 = v10 ? xc[o10] : 0.0f;
                float a11 = v11 ? xc[o11] : 0.0f;
                srow[ci * 68] = a00 * w00 + a01 * w01 + a10 * w10 + a11 * w11;
            }
        }
        __syncthreads();

        // ---- Phase C: 8o x 8p register-tiled rank-1 updates ----
        const float* wp = g_wT + kk * Cn * On + o0;
        const float* sp = S + p0;
#pragma unroll 2
        for (int c = 0; c < Cn; c++) {
            const ulonglong2* w2 = (const ulonglong2*)(wp + c * On);
            ulonglong2 wa = w2[0];           // (o0,o0+1),(o0+2,o0+3)
            ulonglong2 wb = w2[1];           // (o0+4,o0+5),(o0+6,o0+7)
            const float4* s4 = (const float4*)(sp + c * 68);
            float4 sv0 = s4[0];
            float4 sv1 = s4[1];
            u64t s[8];
            s[0] = pack2(sv0.x, sv0.x); s[1] = pack2(sv0.y, sv0.y);
            s[2] = pack2(sv0.z, sv0.z); s[3] = pack2(sv0.w, sv0.w);
            s[4] = pack2(sv1.x, sv1.x); s[5] = pack2(sv1.y, sv1.y);
            s[6] = pack2(sv1.z, sv1.z); s[7] = pack2(sv1.w, sv1.w);
#pragma unroll
            for (int j = 0; j < 8; j++) {
                acc2[0 * 8 + j] = ffma2(wa.x, s[j], acc2[0 * 8 + j]);
                acc2[1 * 8 + j] = ffma2(wa.y, s[j], acc2[1 * 8 + j]);
                acc2[2 * 8 + j] = ffma2(wb.x, s[j], acc2[2 * 8 + j]);
                acc2[3 * 8 + j] = ffma2(wb.y, s[j], acc2[3 * 8 + j]);
            }
        }
        __syncthreads();
    }

    // ---- Epilogue: unpack into smem (reuse S as [o][68]), coalesced stores ----
#pragma unroll
    for (int i = 0; i < 4; i++)
#pragma unroll
        for (int j = 0; j < 8; j++) {
            float lo, hi;
            unpack2(acc2[i * 8 + j], lo, hi);
            S[(o0 + 2 * i)     * 68 + p0 + j] = lo;
            S[(o0 + 2 * i + 1) * 68 + p0 + j] = hi;
        }
    __syncthreads();

    float* ob = out + ((size_t)(b * On) * Hn + h) * Wn;
    for (int i = tid; i < On * 64; i += 128) {
        int o = i >> 6, p = i & 63;
        ob[(size_t)o * Hn * Wn + p] = S[o * 68 + p];
    }
}

// ---------------------------------------------------------------------------
extern "C" void kernel_launch(void* const* d_in, const int* in_sizes, int n_in,
                              void* d_out, int out_size) {
    const float* x     = (const float*)d_in[0];
    const float* w_off = (const float*)d_in[1];
    const float* b_off = (const float*)d_in[2];
    const float* w_def = (const float*)d_in[3];
    const float* b_def = (const float*)d_in[4];
    float* out = (float*)d_out;

    off_kernel<<<512, 256>>>(x, w_off, b_off, w_def);
    main_kernel<<<Bn * Hn, 128>>>(x, b_def, out);
}

// round 6
// speedup vs baseline: 2.3404x; 1.5062x over previous
#include <cuda_runtime.h>
#include <cuda_bf16.h>
#include <cstdint>

#define KK9 9
#define NJ  18
#define Bn  8
#define Cn  128
#define Hn  64
#define Wn  64
#define On  128
#define NCHUNK 4
#define KSLOTS 384               // 128 c * 3 split slots per kk
#define NSTEPS 24                // KSLOTS / 16
#define BROWB 144                // bytes per B row (64 p * 2B + 16 pad)
#define BROWS 72                 // ushorts per B row

// ---------------- scratch (no allocations allowed) ---------------------------
__device__ float g_off_part[NCHUNK * Bn * NJ * Hn * Wn];
// A fragments, fragment-major: [kk][kstep][mtile(8)][lane(32)] -> uint4 {a0,a1,a2,a3}
__device__ uint4 g_wAfrag[KK9 * NSTEPS * 8 * 32];

// ---------------- smem layout for main kernel (dynamic) ----------------------
#define SMB_BYTES (KSLOTS * BROWB)        // 55296
#define SM_IY  SMB_BYTES
#define SM_IX  (SM_IY + 2304)
#define SM_WY  (SM_IX + 2304)
#define SM_WX  (SM_WY + 2304)
#define SM_TOT (SM_WX + 2304)             // 64512 B

// ---------------- helpers -----------------------------------------------------
typedef unsigned long long u64t;
__device__ __forceinline__ u64t pack2(float a, float b) {
    u64t r; asm("mov.b64 %0, {%1, %2};" : "=l"(r) : "f"(a), "f"(b)); return r;
}
__device__ __forceinline__ u64t ffma2(u64t a, u64t b, u64t c) {
    u64t d; asm("fma.rn.f32x2 %0, %1, %2, %3;" : "=l"(d) : "l"(a), "l"(b), "l"(c)); return d;
}
__device__ __forceinline__ void unpack2(u64t v, float& lo, float& hi) {
    asm("mov.b64 {%0, %1}, %2;" : "=f"(lo), "=f"(hi) : "l"(v));
}
__device__ __forceinline__ uint32_t smem_u32(const void* p) {
    uint32_t a;
    asm("{ .reg .u64 t; cvta.to.shared.u64 t, %1; cvt.u32.u64 %0, t; }" : "=r"(a) : "l"(p));
    return a;
}
// A-slot value for k-slot (3 per channel): (hi, lo, hi)
__device__ __forceinline__ unsigned short aval(const float* w_def, int kk, int m, int kslot) {
    int c = kslot / 3;
    int s = kslot - 3 * c;
    float w = w_def[(m * Cn + c) * KK9 + kk];
    __nv_bfloat16 hi = __float2bfloat16(w);
    if (s == 1) {
        __nv_bfloat16 lo = __float2bfloat16(w - __bfloat162float(hi));
        return __bfloat16_as_ushort(lo);
    }
    return __bfloat16_as_ushort(hi);
}
__device__ __forceinline__ uint32_t apack(const float* w_def, int kk, int m, int kslot) {
    uint32_t lo = aval(w_def, kk, m, kslot);
    uint32_t hi = aval(w_def, kk, m, kslot + 1);
    return lo | (hi << 16);
}

#define MMA_BF16(d, a, b0r, b1r)                                                     \
    asm volatile("mma.sync.aligned.m16n8k16.row.col.f32.bf16.bf16.f32 "              \
                 "{%0,%1,%2,%3}, {%4,%5,%6,%7}, {%8,%9}, {%0,%1,%2,%3};"             \
                 : "+f"((d)[0]), "+f"((d)[1]), "+f"((d)[2]), "+f"((d)[3])            \
                 : "r"((a).x), "r"((a).y), "r"((a).z), "r"((a).w), "r"(b0r), "r"(b1r))

#define LDSM_X4_TRANS(r0, r1, r2, r3, addr)                                          \
    asm volatile("ldmatrix.sync.aligned.m8n8.x4.trans.shared.b16 {%0,%1,%2,%3}, [%4];" \
                 : "=r"(r0), "=r"(r1), "=r"(r2), "=r"(r3) : "r"(addr))

// ---------------------------------------------------------------------------
// Kernel 1: offset conv partials (+ fused A-fragment prep)
// grid = 512 (128 pixel-blocks x 4 channel-chunks), 256 threads
// ---------------------------------------------------------------------------
__global__ __launch_bounds__(256) void off_kernel(const float* __restrict__ x,
                                                  const float* __restrict__ w_off,
                                                  const float* __restrict__ b_off,
                                                  const float* __restrict__ w_def) {
    // prep: w_def -> fragment-major bf16 split A image
    {
        int gt = blockIdx.x * 256 + threadIdx.x;
        for (int it = gt; it < KK9 * NSTEPS * 8 * 32; it += 512 * 256) {
            int lane = it & 31;
            int mt   = (it >> 5) & 7;
            int rest = it >> 8;                 // kk*NSTEPS + ks
            int ks   = rest % NSTEPS;
            int kk   = rest / NSTEPS;
            int g  = lane >> 2, tg = lane & 3;
            int kb = ks * 16 + 2 * tg;
            uint4 v;
            v.x = apack(w_def, kk, mt * 16 + g,     kb);
            v.y = apack(w_def, kk, mt * 16 + g + 8, kb);
            v.z = apack(w_def, kk, mt * 16 + g,     kb + 8);
            v.w = apack(w_def, kk, mt * 16 + g + 8, kb + 8);
            g_wAfrag[it] = v;
        }
    }

    __shared__ u64t wch2[32 * KK9 * 10];

    int chunk = blockIdx.x >> 7;
    int pixblk = blockIdx.x & 127;
    int cc = chunk * 32;

    int pix = pixblk * 256 + threadIdx.x;
    int w = pix & 63;
    int h = (pix >> 6) & 63;
    int b = pix >> 12;

    for (int i = threadIdx.x; i < 32 * KK9 * 9; i += 256) {
        int q  = i % 9;
        int jp = (i / 9) % KK9;
        int cl = i / (9 * KK9);
        float lo = w_off[((2 * jp)     * Cn + cc + cl) * 9 + q];
        float hi = w_off[((2 * jp + 1) * Cn + cc + cl) * 9 + q];
        wch2[(cl * KK9 + jp) * 10 + q] = pack2(lo, hi);
    }
    __syncthreads();

    u64t acc2[KK9];
#pragma unroll
    for (int jp = 0; jp < KK9; jp++)
        acc2[jp] = (chunk == 0) ? pack2(b_off[2 * jp], b_off[2 * jp + 1]) : 0ULL;

    for (int cl = 0; cl < 32; cl++) {
        const float* xb = x + ((b * Cn + cc + cl) * Hn) * Wn;
        u64t x2[9];
#pragma unroll
        for (int ky = 0; ky < 3; ky++)
#pragma unroll
            for (int kx = 0; kx < 3; kx++) {
                int y = h - 1 + ky, xx = w - 1 + kx;
                bool v = (y >= 0) & (y < Hn) & (xx >= 0) & (xx < Wn);
                float xv = v ? xb[y * Wn + xx] : 0.0f;
                x2[ky * 3 + kx] = pack2(xv, xv);
            }
#pragma unroll
        for (int jp = 0; jp < KK9; jp++) {
            const u64t* wp = &wch2[(cl * KK9 + jp) * 10];
            ulonglong2 w01 = *(const ulonglong2*)(wp);
            ulonglong2 w23 = *(const ulonglong2*)(wp + 2);
            ulonglong2 w45 = *(const ulonglong2*)(wp + 4);
            ulonglong2 w67 = *(const ulonglong2*)(wp + 6);
            u64t       w8  = wp[8];
            u64t a = acc2[jp];
            a = ffma2(w01.x, x2[0], a);
            a = ffma2(w01.y, x2[1], a);
            a = ffma2(w23.x, x2[2], a);
            a = ffma2(w23.y, x2[3], a);
            a = ffma2(w45.x, x2[4], a);
            a = ffma2(w45.y, x2[5], a);
            a = ffma2(w67.x, x2[6], a);
            a = ffma2(w67.y, x2[7], a);
            a = ffma2(w8,    x2[8], a);
            acc2[jp] = a;
        }
    }

    float* op = g_off_part + (size_t)chunk * Bn * NJ * Hn * Wn;
#pragma unroll
    for (int jp = 0; jp < KK9; jp++) {
        float lo, hi;
        unpack2(acc2[jp], lo, hi);
        op[((b * NJ + 2 * jp)     * Hn + h) * Wn + w] = lo;
        op[((b * NJ + 2 * jp + 1) * Hn + h) * Wn + w] = hi;
    }
}

// ---------------------------------------------------------------------------
// Kernel 2: gather (bf16 split into smem B[k][p]) + mma.sync bf16 GEMM.
// Block 256 thr = 8 warps (4m x 2n). Tile M=128 o x N=64 p, K = 9*384.
// ---------------------------------------------------------------------------
__global__ __launch_bounds__(256) void main_kernel(const float* __restrict__ x,
                                                   const float* __restrict__ b_def,
                                                   float* __restrict__ out) {
    extern __shared__ char sm[];
    unsigned short* sB = (unsigned short*)sm;
    uint32_t smB = smem_u32(sm);

    int tid  = threadIdx.x;
    int wid  = tid >> 5;
    int lane = tid & 31;
    int b = blockIdx.x >> 6;
    int h = blockIdx.x & 63;

    int*   s_iy0 = (int*)(sm + SM_IY);
    int*   s_ix0 = (int*)(sm + SM_IX);
    float* s_wy  = (float*)(sm + SM_WY);
    float* s_wx  = (float*)(sm + SM_WX);

    // ---- Phase A: sampling metadata (sum 4 offset partials) ----
    for (int i = tid; i < 64 * KK9; i += 256) {
        int p  = i / KK9, kk = i % KK9;
        int ky = kk / 3,  kx = kk % 3;
        size_t base_y = ((size_t)(b * NJ + 2 * kk)     * Hn + h) * Wn + p;
        size_t base_x = ((size_t)(b * NJ + 2 * kk + 1) * Hn + h) * Wn + p;
        const size_t CS = (size_t)Bn * NJ * Hn * Wn;
        float offy = g_off_part[base_y] + g_off_part[CS + base_y]
                   + g_off_part[2 * CS + base_y] + g_off_part[3 * CS + base_y];
        float offx = g_off_part[base_x] + g_off_part[CS + base_x]
                   + g_off_part[2 * CS + base_x] + g_off_part[3 * CS + base_x];
        float py = (float)(h - 1 + ky) + offy;
        float px = (float)(p - 1 + kx) + offx;
        float fy = floorf(py), fx = floorf(px);
        s_iy0[i] = (int)fy;
        s_ix0[i] = (int)fx;
        s_wy[i]  = py - fy;
        s_wx[i]  = px - fx;
    }
    __syncthreads();

    // warp tiling: 4m x 2n
    int wm = wid >> 1;                   // 0..3 -> o block of 32
    int wn = wid & 1;                    // 0..1 -> p block of 32
    int g  = lane >> 2, tg = lane & 3;

    float acc[2][4][4];
#pragma unroll
    for (int f = 0; f < 2; f++)
#pragma unroll
        for (int nf = 0; nf < 4; nf++)
#pragma unroll
            for (int q = 0; q < 4; q++) acc[f][nf][q] = 0.0f;

    // gather mapping: thread = (pixel, 32-channel group)
    int p    = tid & 63;
    int cgrp = tid >> 6;
    const float* xb0 = x + (size_t)(b * Cn + cgrp * 32) * Hn * Wn;

    // ldmatrix per-lane row offset (constant across ksteps except +ks*2304)
    int  lr    = lane & 7;
    int  khalf = ((lane >> 3) & 1) * 8;
    int  pgrp  = lane >> 4;
    uint32_t browoff = smB + (uint32_t)((khalf + lr) * BROWB + (wn * 32 + pgrp * 8) * 2);

    for (int kk = 0; kk < KK9; kk++) {
        // ---- Phase B: gather 32 channels for pixel p; write bf16 split rows ----
        {
            int m = p * KK9 + kk;
            int iy0 = s_iy0[m], ix0 = s_ix0[m];
            float wy = s_wy[m], wx = s_wx[m];
            float w00 = (1.f - wy) * (1.f - wx);
            float w01 = (1.f - wy) * wx;
            float w10 = wy * (1.f - wx);
            float w11 = wy * wx;
            int iy1 = iy0 + 1, ix1 = ix0 + 1;
            bool vy0 = (iy0 >= 0) & (iy0 < Hn), vy1 = (iy1 >= 0) & (iy1 < Hn);
            bool vx0 = (ix0 >= 0) & (ix0 < Wn), vx1 = (ix1 >= 0) & (ix1 < Wn);
            bool v00 = vy0 & vx0, v01 = vy0 & vx1, v10 = vy1 & vx0, v11 = vy1 & vx1;
            int o00 = iy0 * Wn + ix0, o01 = iy0 * Wn + ix1;
            int o10 = iy1 * Wn + ix0, o11 = iy1 * Wn + ix1;

#pragma unroll 4
            for (int ci = 0; ci < 32; ci++) {
                const float* xc = xb0 + ci * (Hn * Wn);
                float a00 = v00 ? xc[o00] : 0.0f;
                float a01 = v01 ? xc[o01] : 0.0f;
                float a10 = v10 ? xc[o10] : 0.0f;
                float a11 = v11 ? xc[o11] : 0.0f;
                float s = a00 * w00 + a01 * w01 + a10 * w10 + a11 * w11;
                __nv_bfloat16 hb16 = __float2bfloat16(s);
                unsigned short hb = __bfloat16_as_ushort(hb16);
                unsigned short lb = __bfloat16_as_ushort(
                    __float2bfloat16(s - __bfloat162float(hb16)));
                int c = cgrp * 32 + ci;
                int base = 3 * c * BROWS + p;        // B row-major [kslot][p]
                sB[base]             = hb;           // slot 3c   : s_hi (pairs w_hi)
                sB[base + BROWS]     = hb;           // slot 3c+1 : s_hi (pairs w_lo)
                sB[base + 2 * BROWS] = lb;           // slot 3c+2 : s_lo (pairs w_hi)
            }
        }
        __syncthreads();

        // ---- Phase C: 24 k16 MMA steps ----
        const uint4* ap = g_wAfrag + (((size_t)kk * NSTEPS) * 8 + wm * 2) * 32 + lane;
#pragma unroll 4
        for (int ks = 0; ks < NSTEPS; ks++) {
            uint4 A0 = ap[0];
            uint4 A1 = ap[32];
            ap += 256;

            uint32_t addr = browoff + (uint32_t)(ks * 16 * BROWB);
            uint32_t b0, b1, b2, b3, c0, c1, c2, c3;
            LDSM_X4_TRANS(b0, b1, b2, b3, addr);          // n-frags 0,1
            LDSM_X4_TRANS(c0, c1, c2, c3, addr + 32);     // n-frags 2,3

            MMA_BF16(acc[0][0], A0, b0, b1);
            MMA_BF16(acc[0][1], A0, b2, b3);
            MMA_BF16(acc[0][2], A0, c0, c1);
            MMA_BF16(acc[0][3], A0, c2, c3);
            MMA_BF16(acc[1][0], A1, b0, b1);
            MMA_BF16(acc[1][1], A1, b2, b3);
            MMA_BF16(acc[1][2], A1, c0, c1);
            MMA_BF16(acc[1][3], A1, c2, c3);
        }
        __syncthreads();                                   // B reused next kk
    }

    // ---- Epilogue: D fragment -> gmem with bias ----
#pragma unroll
    for (int f = 0; f < 2; f++) {
        int oo = wm * 32 + f * 16 + g;
        float bd0 = b_def[oo];
        float bd1 = b_def[oo + 8];
        float* orow0 = out + (((size_t)b * On + oo) * Hn + h) * Wn;
        float* orow1 = orow0 + (size_t)8 * Hn * Wn;
#pragma unroll
        for (int nf = 0; nf < 4; nf++) {
            int pp = wn * 32 + nf * 8 + 2 * tg;
            float2 v0 = { acc[f][nf][0] + bd0, acc[f][nf][1] + bd0 };
            float2 v1 = { acc[f][nf][2] + bd1, acc[f][nf][3] + bd1 };
            *(float2*)(orow0 + pp) = v0;
            *(float2*)(orow1 + pp) = v1;
        }
    }
}

// ---------------------------------------------------------------------------
extern "C" void kernel_launch(void* const* d_in, const int* in_sizes, int n_in,
                              void* d_out, int out_size) {
    const float* x     = (const float*)d_in[0];
    const float* w_off = (const float*)d_in[1];
    const float* b_off = (const float*)d_in[2];
    const float* w_def = (const float*)d_in[3];
    const float* b_def = (const float*)d_in[4];
    float* out = (float*)d_out;

    cudaFuncSetAttribute(main_kernel, cudaFuncAttributeMaxDynamicSharedMemorySize, SM_TOT);

    off_kernel<<<512, 256>>>(x, w_off, b_off, w_def);
    main_kernel<<<Bn * Hn, 256, SM_TOT>>>(x, b_def, out);
}

// round 7
// speedup vs baseline: 3.0464x; 1.3017x over previous
#include <cuda_runtime.h>
#include <cuda_bf16.h>
#include <cstdint>

#define KK9 9
#define NJ  18
#define Bn  8
#define Cn  128
#define Hn  64
#define Wn  64
#define On  128
#define HW  (Hn * Wn)
#define NCHUNK 4
#define KSLOTS 384               // 128 c * 3 split slots per kk
#define NSTEPS 24                // KSLOTS / 16
#define BROWB 144                // bytes per B row (64 p * 2B + 16 pad)
#define BROWS 72                 // ushorts per B row
#define SMB_BYTES (KSLOTS * BROWB)       // 55296 per buffer
#define SMB_HALF_SHORTS (SMB_BYTES / 2)  // 27648 shorts per buffer
#define SM_TOT (2 * SMB_BYTES)           // 110592 B (double-buffered)

// ---------------- scratch (no allocations allowed) ---------------------------
__device__ float g_off_part[NCHUNK * Bn * NJ * Hn * Wn];
// A fragments, fragment-major: [kk][kstep][mtile(8)][lane(32)] -> uint4
__device__ uint4 g_wAfrag[KK9 * NSTEPS * 8 * 32];

// ---------------- helpers -----------------------------------------------------
typedef unsigned long long u64t;
__device__ __forceinline__ u64t pack2(float a, float b) {
    u64t r; asm("mov.b64 %0, {%1, %2};" : "=l"(r) : "f"(a), "f"(b)); return r;
}
__device__ __forceinline__ u64t ffma2(u64t a, u64t b, u64t c) {
    u64t d; asm("fma.rn.f32x2 %0, %1, %2, %3;" : "=l"(d) : "l"(a), "l"(b), "l"(c)); return d;
}
__device__ __forceinline__ void unpack2(u64t v, float& lo, float& hi) {
    asm("mov.b64 {%0, %1}, %2;" : "=f"(lo), "=f"(hi) : "l"(v));
}
__device__ __forceinline__ uint32_t smem_u32(const void* p) {
    uint32_t a;
    asm("{ .reg .u64 t; cvta.to.shared.u64 t, %1; cvt.u32.u64 %0, t; }" : "=r"(a) : "l"(p));
    return a;
}
__device__ __forceinline__ unsigned short aval(const float* w_def, int kk, int m, int kslot) {
    int c = kslot / 3;
    int s = kslot - 3 * c;
    float w = w_def[(m * Cn + c) * KK9 + kk];
    __nv_bfloat16 hi = __float2bfloat16(w);
    if (s == 1) {
        __nv_bfloat16 lo = __float2bfloat16(w - __bfloat162float(hi));
        return __bfloat16_as_ushort(lo);
    }
    return __bfloat16_as_ushort(hi);
}
__device__ __forceinline__ uint32_t apack(const float* w_def, int kk, int m, int kslot) {
    uint32_t lo = aval(w_def, kk, m, kslot);
    uint32_t hi = aval(w_def, kk, m, kslot + 1);
    return lo | (hi << 16);
}

#define MMA_BF16(d, a, b0r, b1r)                                                     \
    asm volatile("mma.sync.aligned.m16n8k16.row.col.f32.bf16.bf16.f32 "              \
                 "{%0,%1,%2,%3}, {%4,%5,%6,%7}, {%8,%9}, {%0,%1,%2,%3};"             \
                 : "+f"((d)[0]), "+f"((d)[1]), "+f"((d)[2]), "+f"((d)[3])            \
                 : "r"((a).x), "r"((a).y), "r"((a).z), "r"((a).w), "r"(b0r), "r"(b1r))

#define LDSM_X4_TRANS(r0, r1, r2, r3, addr)                                          \
    asm volatile("ldmatrix.sync.aligned.m8n8.x4.trans.shared.b16 {%0,%1,%2,%3}, [%4];" \
                 : "=r"(r0), "=r"(r1), "=r"(r2), "=r"(r3) : "r"(addr))

// sampling metadata, recomputed per (p, kk) from offset partials
struct Meta {
    float w00, w01, w10, w11;
    int   o00, o01, o10, o11;
    bool  v00, v01, v10, v11;
};
__device__ __forceinline__ Meta make_meta(int b, int h, int p, int kk) {
    const size_t CS = (size_t)Bn * NJ * Hn * Wn;
    int ky = kk / 3, kx = kk % 3;
    size_t by = ((size_t)(b * NJ + 2 * kk) * Hn + h) * Wn + p;
    size_t bx = by + (size_t)HW;
    float offy = g_off_part[by] + g_off_part[CS + by]
               + g_off_part[2 * CS + by] + g_off_part[3 * CS + by];
    float offx = g_off_part[bx] + g_off_part[CS + bx]
               + g_off_part[2 * CS + bx] + g_off_part[3 * CS + bx];
    float py = (float)(h - 1 + ky) + offy;
    float px = (float)(p - 1 + kx) + offx;
    float fy = floorf(py), fx = floorf(px);
    int iy0 = (int)fy, ix0 = (int)fx;
    float wy = py - fy, wx = px - fx;
    Meta m;
    m.w00 = (1.f - wy) * (1.f - wx);
    m.w01 = (1.f - wy) * wx;
    m.w10 = wy * (1.f - wx);
    m.w11 = wy * wx;
    int iy1 = iy0 + 1, ix1 = ix0 + 1;
    bool vy0 = (iy0 >= 0) & (iy0 < Hn), vy1 = (iy1 >= 0) & (iy1 < Hn);
    bool vx0 = (ix0 >= 0) & (ix0 < Wn), vx1 = (ix1 >= 0) & (ix1 < Wn);
    m.v00 = vy0 & vx0; m.v01 = vy0 & vx1; m.v10 = vy1 & vx0; m.v11 = vy1 & vx1;
    m.o00 = iy0 * Wn + ix0; m.o01 = iy0 * Wn + ix1;
    m.o10 = iy1 * Wn + ix0; m.o11 = iy1 * Wn + ix1;
    return m;
}
__device__ __forceinline__ void bsplit_store(unsigned short* dst, int c, int p, float s) {
    __nv_bfloat16 hb16 = __float2bfloat16(s);
    unsigned short hb = __bfloat16_as_ushort(hb16);
    unsigned short lb = __bfloat16_as_ushort(__float2bfloat16(s - __bfloat162float(hb16)));
    int base = 3 * c * BROWS + p;
    dst[base]             = hb;
    dst[base + BROWS]     = hb;
    dst[base + 2 * BROWS] = lb;
}

// ---------------------------------------------------------------------------
// Kernel 1: offset conv partials (+ fused A-fragment prep) — unchanged
// ---------------------------------------------------------------------------
__global__ __launch_bounds__(256) void off_kernel(const float* __restrict__ x,
                                                  const float* __restrict__ w_off,
                                                  const float* __restrict__ b_off,
                                                  const float* __restrict__ w_def) {
    {
        int gt = blockIdx.x * 256 + threadIdx.x;
        for (int it = gt; it < KK9 * NSTEPS * 8 * 32; it += 512 * 256) {
            int lane = it & 31;
            int mt   = (it >> 5) & 7;
            int rest = it >> 8;
            int ks   = rest % NSTEPS;
            int kk   = rest / NSTEPS;
            int g  = lane >> 2, tg = lane & 3;
            int kb = ks * 16 + 2 * tg;
            uint4 v;
            v.x = apack(w_def, kk, mt * 16 + g,     kb);
            v.y = apack(w_def, kk, mt * 16 + g + 8, kb);
            v.z = apack(w_def, kk, mt * 16 + g,     kb + 8);
            v.w = apack(w_def, kk, mt * 16 + g + 8, kb + 8);
            g_wAfrag[it] = v;
        }
    }

    __shared__ u64t wch2[32 * KK9 * 10];

    int chunk = blockIdx.x >> 7;
    int pixblk = blockIdx.x & 127;
    int cc = chunk * 32;

    int pix = pixblk * 256 + threadIdx.x;
    int w = pix & 63;
    int h = (pix >> 6) & 63;
    int b = pix >> 12;

    for (int i = threadIdx.x; i < 32 * KK9 * 9; i += 256) {
        int q  = i % 9;
        int jp = (i / 9) % KK9;
        int cl = i / (9 * KK9);
        float lo = w_off[((2 * jp)     * Cn + cc + cl) * 9 + q];
        float hi = w_off[((2 * jp + 1) * Cn + cc + cl) * 9 + q];
        wch2[(cl * KK9 + jp) * 10 + q] = pack2(lo, hi);
    }
    __syncthreads();

    u64t acc2[KK9];
#pragma unroll
    for (int jp = 0; jp < KK9; jp++)
        acc2[jp] = (chunk == 0) ? pack2(b_off[2 * jp], b_off[2 * jp + 1]) : 0ULL;

    for (int cl = 0; cl < 32; cl++) {
        const float* xb = x + ((b * Cn + cc + cl) * Hn) * Wn;
        u64t x2[9];
#pragma unroll
        for (int ky = 0; ky < 3; ky++)
#pragma unroll
            for (int kx = 0; kx < 3; kx++) {
                int y = h - 1 + ky, xx = w - 1 + kx;
                bool v = (y >= 0) & (y < Hn) & (xx >= 0) & (xx < Wn);
                float xv = v ? xb[y * Wn + xx] : 0.0f;
                x2[ky * 3 + kx] = pack2(xv, xv);
            }
#pragma unroll
        for (int jp = 0; jp < KK9; jp++) {
            const u64t* wp = &wch2[(cl * KK9 + jp) * 10];
            ulonglong2 w01 = *(const ulonglong2*)(wp);
            ulonglong2 w23 = *(const ulonglong2*)(wp + 2);
            ulonglong2 w45 = *(const ulonglong2*)(wp + 4);
            ulonglong2 w67 = *(const ulonglong2*)(wp + 6);
            u64t       w8  = wp[8];
            u64t a = acc2[jp];
            a = ffma2(w01.x, x2[0], a);
            a = ffma2(w01.y, x2[1], a);
            a = ffma2(w23.x, x2[2], a);
            a = ffma2(w23.y, x2[3], a);
            a = ffma2(w45.x, x2[4], a);
            a = ffma2(w45.y, x2[5], a);
            a = ffma2(w67.x, x2[6], a);
            a = ffma2(w67.y, x2[7], a);
            a = ffma2(w8,    x2[8], a);
            acc2[jp] = a;
        }
    }

    float* op = g_off_part + (size_t)chunk * Bn * NJ * Hn * Wn;
#pragma unroll
    for (int jp = 0; jp < KK9; jp++) {
        float lo, hi;
        unpack2(acc2[jp], lo, hi);
        op[((b * NJ + 2 * jp)     * Hn + h) * Wn + w] = lo;
        op[((b * NJ + 2 * jp + 1) * Hn + h) * Wn + w] = hi;
    }
}

// ---------------------------------------------------------------------------
// Kernel 2: software-pipelined gather + mma.sync bf16 GEMM, double-buffered B.
// Block 256 thr = 8 warps (4m x 2n). Tile M=128 o x N=64 p, K = 9*384.
// Per kk: LDGs for kk+1 issue before MMA chunks of kk, STS after -> latency hidden.
// ---------------------------------------------------------------------------
__global__ __launch_bounds__(256, 2) void main_kernel(const float* __restrict__ x,
                                                      const float* __restrict__ b_def,
                                                      float* __restrict__ out) {
    extern __shared__ char sm[];
    unsigned short* sB = (unsigned short*)sm;
    uint32_t smB = smem_u32(sm);

    int tid  = threadIdx.x;
    int wid  = tid >> 5;
    int lane = tid & 31;
    int b = blockIdx.x >> 6;
    int h = blockIdx.x & 63;

    // warp tiling: 4m x 2n
    int wm = wid >> 1;
    int wn = wid & 1;
    int g  = lane >> 2, tg = lane & 3;

    float acc[2][4][4];
#pragma unroll
    for (int f = 0; f < 2; f++)
#pragma unroll
        for (int nf = 0; nf < 4; nf++)
#pragma unroll
            for (int q = 0; q < 4; q++) acc[f][nf][q] = 0.0f;

    // gather mapping: thread = (pixel p, 32-channel group)
    int p    = tid & 63;
    int cgrp = tid >> 6;
    const float* xb0 = x + (size_t)(b * Cn + cgrp * 32) * HW;

    // ldmatrix per-lane byte offset within a buffer
    int lr    = lane & 7;
    int khalf = ((lane >> 3) & 1) * 8;
    int pgrp  = lane >> 4;
    uint32_t browbase = (uint32_t)((khalf + lr) * BROWB + (wn * 32 + pgrp * 8) * 2);

    // ---- prologue: gather kk=0 into buffer 0 ----
    {
        Meta m0 = make_meta(b, h, p, 0);
#pragma unroll 8
        for (int ci = 0; ci < 32; ci++) {
            const float* xc = xb0 + ci * HW;
            float a00 = m0.v00 ? xc[m0.o00] : 0.0f;
            float a01 = m0.v01 ? xc[m0.o01] : 0.0f;
            float a10 = m0.v10 ? xc[m0.o10] : 0.0f;
            float a11 = m0.v11 ? xc[m0.o11] : 0.0f;
            float s = a00 * m0.w00 + a01 * m0.w01 + a10 * m0.w10 + a11 * m0.w11;
            bsplit_store(sB, cgrp * 32 + ci, p, s);
        }
    }
    __syncthreads();

    // ---- main pipelined loop over kk ----
    for (int kk = 0; kk < KK9; kk++) {
        uint32_t curOff = (uint32_t)((kk & 1) * SMB_BYTES);
        unsigned short* nxtB = sB + ((kk + 1) & 1) * SMB_HALF_SHORTS;
        bool doG = (kk < KK9 - 1);
        Meta mn;
        if (doG) mn = make_meta(b, h, p, kk + 1);
        const uint4* ap = g_wAfrag + ((size_t)kk * NSTEPS * 8 + wm * 2) * 32 + lane;

        for (int chunk = 0; chunk < 8; chunk++) {
            // issue next-kk gather loads (latency overlaps the MMAs below)
            float gv[4][4];
            if (doG) {
#pragma unroll
                for (int q = 0; q < 4; q++) {
                    const float* xc = xb0 + (chunk * 4 + q) * HW;
                    gv[q][0] = mn.v00 ? xc[mn.o00] : 0.0f;
                    gv[q][1] = mn.v01 ? xc[mn.o01] : 0.0f;
                    gv[q][2] = mn.v10 ? xc[mn.o10] : 0.0f;
                    gv[q][3] = mn.v11 ? xc[mn.o11] : 0.0f;
                }
            }

            // 3 k16 MMA steps on current buffer
#pragma unroll
            for (int s3 = 0; s3 < 3; s3++) {
                int ks = chunk * 3 + s3;
                uint4 A0 = ap[(size_t)ks * 256];
                uint4 A1 = ap[(size_t)ks * 256 + 32];
                uint32_t addr = smB + curOff + browbase + (uint32_t)(ks * 16 * BROWB);
                uint32_t b0, b1, b2, b3, c0, c1, c2, c3;
                LDSM_X4_TRANS(b0, b1, b2, b3, addr);
                LDSM_X4_TRANS(c0, c1, c2, c3, addr + 32);
                MMA_BF16(acc[0][0], A0, b0, b1);
                MMA_BF16(acc[0][1], A0, b2, b3);
                MMA_BF16(acc[0][2], A0, c0, c1);
                MMA_BF16(acc[0][3], A0, c2, c3);
                MMA_BF16(acc[1][0], A1, b0, b1);
                MMA_BF16(acc[1][1], A1, b2, b3);
                MMA_BF16(acc[1][2], A1, c0, c1);
                MMA_BF16(acc[1][3], A1, c2, c3);
            }

            // consume gathered values: combine + split-store into next buffer
            if (doG) {
#pragma unroll
                for (int q = 0; q < 4; q++) {
                    float s = gv[q][0] * mn.w00 + gv[q][1] * mn.w01
                            + gv[q][2] * mn.w10 + gv[q][3] * mn.w11;
                    bsplit_store(nxtB, cgrp * 32 + chunk * 4 + q, p, s);
                }
            }
        }
        __syncthreads();
    }

    // ---- Epilogue: D fragment -> gmem with bias ----
#pragma unroll
    for (int f = 0; f < 2; f++) {
        int oo = wm * 32 + f * 16 + g;
        float bd0 = b_def[oo];
        float bd1 = b_def[oo + 8];
        float* orow0 = out + (((size_t)b * On + oo) * Hn + h) * Wn;
        float* orow1 = orow0 + (size_t)8 * HW;
#pragma unroll
        for (int nf = 0; nf < 4; nf++) {
            int pp = wn * 32 + nf * 8 + 2 * tg;
            float2 v0 = { acc[f][nf][0] + bd0, acc[f][nf][1] + bd0 };
            float2 v1 = { acc[f][nf][2] + bd1, acc[f][nf][3] + bd1 };
            *(float2*)(orow0 + pp) = v0;
            *(float2*)(orow1 + pp) = v1;
        }
    }
}

// ---------------------------------------------------------------------------
extern "C" void kernel_launch(void* const* d_in, const int* in_sizes, int n_in,
                              void* d_out, int out_size) {
    const float* x     = (const float*)d_in[0];
    const float* w_off = (const float*)d_in[1];
    const float* b_off = (const float*)d_in[2];
    const float* w_def = (const float*)d_in[3];
    const float* b_def = (const float*)d_in[4];
    float* out = (float*)d_out;

    cudaFuncSetAttribute(main_kernel, cudaFuncAttributeMaxDynamicSharedMemorySize, SM_TOT);

    off_kernel<<<512, 256>>>(x, w_off, b_off, w_def);
    main_kernel<<<Bn * Hn, 256, SM_TOT>>>(x, b_def, out);
}

// round 8
// speedup vs baseline: 3.4559x; 1.1344x over previous
#include <cuda_runtime.h>
#include <cuda_bf16.h>
#include <cstdint>

#define KK9 9
#define NJ  18
#define Bn  8
#define Cn  128
#define Hn  64
#define Wn  64
#define On  128
#define HW  (Hn * Wn)
#define NCHUNK 4
#define BROWB 144                // bytes per B row (64 p * 2B + 16 pad)
#define BROWS 72                 // ushorts per B row
#define SMB_BYTES (256 * BROWB)          // 36864 per buffer (128 hi + 128 lo rows)
#define SMB_HALF_SHORTS (SMB_BYTES / 2)  // shorts per buffer
#define SM_TOT (2 * SMB_BYTES)           // 73728 B double-buffered

// ---------------- scratch (no allocations allowed) ---------------------------
__device__ float g_off_part[NCHUNK * Bn * NJ * Hn * Wn];
// A fragments: [kk][ks8(8)][reg(2: hi,lo)][mtile(8)][lane(32)] -> uint4
__device__ uint4 g_wAfrag[KK9 * 8 * 2 * 8 * 32];

// ---------------- helpers -----------------------------------------------------
typedef unsigned long long u64t;
__device__ __forceinline__ u64t pack2(float a, float b) {
    u64t r; asm("mov.b64 %0, {%1, %2};" : "=l"(r) : "f"(a), "f"(b)); return r;
}
__device__ __forceinline__ u64t ffma2(u64t a, u64t b, u64t c) {
    u64t d; asm("fma.rn.f32x2 %0, %1, %2, %3;" : "=l"(d) : "l"(a), "l"(b), "l"(c)); return d;
}
__device__ __forceinline__ void unpack2(u64t v, float& lo, float& hi) {
    asm("mov.b64 {%0, %1}, %2;" : "=f"(lo), "=f"(hi) : "l"(v));
}
__device__ __forceinline__ uint32_t smem_u32(const void* p) {
    uint32_t a;
    asm("{ .reg .u64 t; cvta.to.shared.u64 t, %1; cvt.u32.u64 %0, t; }" : "=r"(a) : "l"(p));
    return a;
}
__device__ __forceinline__ unsigned short aval2(const float* w_def, int kk, int m, int c, int reg) {
    float w = w_def[(m * Cn + c) * KK9 + kk];
    __nv_bfloat16 hi = __float2bfloat16(w);
    if (reg) {
        __nv_bfloat16 lo = __float2bfloat16(w - __bfloat162float(hi));
        return __bfloat16_as_ushort(lo);
    }
    return __bfloat16_as_ushort(hi);
}
__device__ __forceinline__ uint32_t apack2(const float* w_def, int kk, int m, int c, int reg) {
    uint32_t lo = aval2(w_def, kk, m, c, reg);
    uint32_t hi = aval2(w_def, kk, m, c + 1, reg);
    return lo | (hi << 16);
}

#define MMA_BF16(d, a, b0r, b1r)                                                     \
    asm volatile("mma.sync.aligned.m16n8k16.row.col.f32.bf16.bf16.f32 "              \
                 "{%0,%1,%2,%3}, {%4,%5,%6,%7}, {%8,%9}, {%0,%1,%2,%3};"             \
                 : "+f"((d)[0]), "+f"((d)[1]), "+f"((d)[2]), "+f"((d)[3])            \
                 : "r"((a).x), "r"((a).y), "r"((a).z), "r"((a).w), "r"(b0r), "r"(b1r))

#define LDSM_X4_TRANS(r0, r1, r2, r3, addr)                                          \
    asm volatile("ldmatrix.sync.aligned.m8n8.x4.trans.shared.b16 {%0,%1,%2,%3}, [%4];" \
                 : "=r"(r0), "=r"(r1), "=r"(r2), "=r"(r3) : "r"(addr))

// sampling metadata recomputed per (p, kk)
struct Meta {
    float w00, w01, w10, w11;
    int   o00, o01, o10, o11;
    bool  v00, v01, v10, v11;
};
__device__ __forceinline__ Meta make_meta(int b, int h, int p, int kk) {
    const size_t CS = (size_t)Bn * NJ * Hn * Wn;
    int ky = kk / 3, kx = kk % 3;
    size_t by = ((size_t)(b * NJ + 2 * kk) * Hn + h) * Wn + p;
    size_t bx = by + (size_t)HW;
    float offy = g_off_part[by] + g_off_part[CS + by]
               + g_off_part[2 * CS + by] + g_off_part[3 * CS + by];
    float offx = g_off_part[bx] + g_off_part[CS + bx]
               + g_off_part[2 * CS + bx] + g_off_part[3 * CS + bx];
    float py = (float)(h - 1 + ky) + offy;
    float px = (float)(p - 1 + kx) + offx;
    float fy = floorf(py), fx = floorf(px);
    int iy0 = (int)fy, ix0 = (int)fx;
    float wy = py - fy, wx = px - fx;
    Meta m;
    m.w00 = (1.f - wy) * (1.f - wx);
    m.w01 = (1.f - wy) * wx;
    m.w10 = wy * (1.f - wx);
    m.w11 = wy * wx;
    int iy1 = iy0 + 1, ix1 = ix0 + 1;
    bool vy0 = (iy0 >= 0) & (iy0 < Hn), vy1 = (iy1 >= 0) & (iy1 < Hn);
    bool vx0 = (ix0 >= 0) & (ix0 < Wn), vx1 = (ix1 >= 0) & (ix1 < Wn);
    m.v00 = vy0 & vx0; m.v01 = vy0 & vx1; m.v10 = vy1 & vx0; m.v11 = vy1 & vx1;
    m.o00 = iy0 * Wn + ix0; m.o01 = iy0 * Wn + ix1;
    m.o10 = iy1 * Wn + ix0; m.o11 = iy1 * Wn + ix1;
    return m;
}
// hi at row c, lo at row 128+c (single store each)
__device__ __forceinline__ void bsplit_store(unsigned short* dst, int c, int p, float s) {
    __nv_bfloat16 hb16 = __float2bfloat16(s);
    unsigned short hb = __bfloat16_as_ushort(hb16);
    unsigned short lb = __bfloat16_as_ushort(__float2bfloat16(s - __bfloat162float(hb16)));
    int base = c * BROWS + p;
    dst[base]               = hb;
    dst[base + 128 * BROWS] = lb;
}

// ---------------------------------------------------------------------------
// Kernel 1: offset conv partials (+ fused A-fragment prep)
// ---------------------------------------------------------------------------
__global__ __launch_bounds__(256) void off_kernel(const float* __restrict__ x,
                                                  const float* __restrict__ w_off,
                                                  const float* __restrict__ b_off,
                                                  const float* __restrict__ w_def) {
    {
        int gt = blockIdx.x * 256 + threadIdx.x;
        for (int it = gt; it < KK9 * 8 * 2 * 8 * 32; it += 512 * 256) {
            int lane = it & 31;
            int mt   = (it >> 5) & 7;
            int reg  = (it >> 8) & 1;
            int ks8  = (it >> 9) & 7;
            int kk   = it >> 12;
            int g  = lane >> 2, tg = lane & 3;
            int cb = ks8 * 16 + 2 * tg;
            int m  = mt * 16 + g;
            uint4 v;
            v.x = apack2(w_def, kk, m,     cb,     reg);
            v.y = apack2(w_def, kk, m + 8, cb,     reg);
            v.z = apack2(w_def, kk, m,     cb + 8, reg);
            v.w = apack2(w_def, kk, m + 8, cb + 8, reg);
            g_wAfrag[it] = v;
        }
    }

    __shared__ u64t wch2[32 * KK9 * 10];

    int chunk = blockIdx.x >> 7;
    int pixblk = blockIdx.x & 127;
    int cc = chunk * 32;

    int pix = pixblk * 256 + threadIdx.x;
    int w = pix & 63;
    int h = (pix >> 6) & 63;
    int b = pix >> 12;

    for (int i = threadIdx.x; i < 32 * KK9 * 9; i += 256) {
        int q  = i % 9;
        int jp = (i / 9) % KK9;
        int cl = i / (9 * KK9);
        float lo = w_off[((2 * jp)     * Cn + cc + cl) * 9 + q];
        float hi = w_off[((2 * jp + 1) * Cn + cc + cl) * 9 + q];
        wch2[(cl * KK9 + jp) * 10 + q] = pack2(lo, hi);
    }
    __syncthreads();

    u64t acc2[KK9];
#pragma unroll
    for (int jp = 0; jp < KK9; jp++)
        acc2[jp] = (chunk == 0) ? pack2(b_off[2 * jp], b_off[2 * jp + 1]) : 0ULL;

    for (int cl = 0; cl < 32; cl++) {
        const float* xb = x + ((b * Cn + cc + cl) * Hn) * Wn;
        u64t x2[9];
#pragma unroll
        for (int ky = 0; ky < 3; ky++)
#pragma unroll
            for (int kx = 0; kx < 3; kx++) {
                int y = h - 1 + ky, xx = w - 1 + kx;
                bool v = (y >= 0) & (y < Hn) & (xx >= 0) & (xx < Wn);
                float xv = v ? xb[y * Wn + xx] : 0.0f;
                x2[ky * 3 + kx] = pack2(xv, xv);
            }
#pragma unroll
        for (int jp = 0; jp < KK9; jp++) {
            const u64t* wp = &wch2[(cl * KK9 + jp) * 10];
            ulonglong2 w01 = *(const ulonglong2*)(wp);
            ulonglong2 w23 = *(const ulonglong2*)(wp + 2);
            ulonglong2 w45 = *(const ulonglong2*)(wp + 4);
            ulonglong2 w67 = *(const ulonglong2*)(wp + 6);
            u64t       w8  = wp[8];
            u64t a = acc2[jp];
            a = ffma2(w01.x, x2[0], a);
            a = ffma2(w01.y, x2[1], a);
            a = ffma2(w23.x, x2[2], a);
            a = ffma2(w23.y, x2[3], a);
            a = ffma2(w45.x, x2[4], a);
            a = ffma2(w45.y, x2[5], a);
            a = ffma2(w67.x, x2[6], a);
            a = ffma2(w67.y, x2[7], a);
            a = ffma2(w8,    x2[8], a);
            acc2[jp] = a;
        }
    }

    float* op = g_off_part + (size_t)chunk * Bn * NJ * Hn * Wn;
#pragma unroll
    for (int jp = 0; jp < KK9; jp++) {
        float lo, hi;
        unpack2(acc2[jp], lo, hi);
        op[((b * NJ + 2 * jp)     * Hn + h) * Wn + w] = lo;
        op[((b * NJ + 2 * jp + 1) * Hn + h) * Wn + w] = hi;
    }
}

// ---------------------------------------------------------------------------
// Kernel 2: pipelined gather + mma.sync bf16 split GEMM with operand reuse.
// B buffer: 256 rows (128 s_hi + 128 s_lo). Per 16-channel step: load
// A_hi/A_lo/B_hi/B_lo once, issue 3 MMA combos from registers.
// ---------------------------------------------------------------------------
__global__ __launch_bounds__(256, 2) void main_kernel(const float* __restrict__ x,
                                                      const float* __restrict__ b_def,
                                                      float* __restrict__ out) {
    extern __shared__ char sm[];
    unsigned short* sB = (unsigned short*)sm;
    uint32_t smB = smem_u32(sm);

    int tid  = threadIdx.x;
    int wid  = tid >> 5;
    int lane = tid & 31;
    int b = blockIdx.x >> 6;
    int h = blockIdx.x & 63;

    // warp tiling: 4m x 2n
    int wm = wid >> 1;
    int wn = wid & 1;
    int g  = lane >> 2, tg = lane & 3;

    float acc[2][4][4];
#pragma unroll
    for (int f = 0; f < 2; f++)
#pragma unroll
        for (int nf = 0; nf < 4; nf++)
#pragma unroll
            for (int q = 0; q < 4; q++) acc[f][nf][q] = 0.0f;

    // gather mapping: thread = (pixel p, 32-channel group)
    int p    = tid & 63;
    int cgrp = tid >> 6;
    const float* xb0 = x + (size_t)(b * Cn + cgrp * 32) * HW;

    // ldmatrix per-lane byte offset within a buffer
    int lr    = lane & 7;
    int khalf = ((lane >> 3) & 1) * 8;
    int pgrp  = lane >> 4;
    uint32_t browbase = (uint32_t)((khalf + lr) * BROWB + (wn * 32 + pgrp * 8) * 2);

    // ---- prologue: gather kk=0 into buffer 0 ----
    {
        Meta m0 = make_meta(b, h, p, 0);
#pragma unroll 8
        for (int ci = 0; ci < 32; ci++) {
            const float* xc = xb0 + ci * HW;
            float a00 = m0.v00 ? xc[m0.o00] : 0.0f;
            float a01 = m0.v01 ? xc[m0.o01] : 0.0f;
            float a10 = m0.v10 ? xc[m0.o10] : 0.0f;
            float a11 = m0.v11 ? xc[m0.o11] : 0.0f;
            float s = a00 * m0.w00 + a01 * m0.w01 + a10 * m0.w10 + a11 * m0.w11;
            bsplit_store(sB, cgrp * 32 + ci, p, s);
        }
    }
    __syncthreads();

    // ---- main pipelined loop over kk ----
    for (int kk = 0; kk < KK9; kk++) {
        uint32_t curOff = (uint32_t)((kk & 1) * SMB_BYTES);
        unsigned short* nxtB = sB + ((kk + 1) & 1) * SMB_HALF_SHORTS;
        bool doG = (kk < KK9 - 1);
        Meta mn;
        if (doG) mn = make_meta(b, h, p, kk + 1);
        const uint4* ap = g_wAfrag + (size_t)kk * (8 * 2 * 8 * 32);

        for (int ks8 = 0; ks8 < 8; ks8++) {
            // issue next-kk gather loads (latency overlaps the MMAs below)
            float gv[4][4];
            if (doG) {
#pragma unroll
                for (int q = 0; q < 4; q++) {
                    const float* xc = xb0 + (ks8 * 4 + q) * HW;
                    gv[q][0] = mn.v00 ? xc[mn.o00] : 0.0f;
                    gv[q][1] = mn.v01 ? xc[mn.o01] : 0.0f;
                    gv[q][2] = mn.v10 ? xc[mn.o10] : 0.0f;
                    gv[q][3] = mn.v11 ? xc[mn.o11] : 0.0f;
                }
            }

            // A fragments: hi + lo (each 2 m-frags)
            const uint4* a_hi = ap + ((size_t)(ks8 * 2)     * 8 + wm * 2) * 32 + lane;
            const uint4* a_lo = ap + ((size_t)(ks8 * 2 + 1) * 8 + wm * 2) * 32 + lane;
            uint4 Ah0 = a_hi[0], Ah1 = a_hi[32];
            uint4 Al0 = a_lo[0], Al1 = a_lo[32];

            // B fragments: hi rows [ks8*16 ..], lo rows offset +128 rows
            uint32_t addr_hi = smB + curOff + browbase + (uint32_t)(ks8 * 16 * BROWB);
            uint32_t addr_lo = addr_hi + (uint32_t)(128 * BROWB);
            uint32_t bh0, bh1, bh2, bh3, bh4, bh5, bh6, bh7;
            uint32_t bl0, bl1, bl2, bl3, bl4, bl5, bl6, bl7;
            LDSM_X4_TRANS(bh0, bh1, bh2, bh3, addr_hi);
            LDSM_X4_TRANS(bh4, bh5, bh6, bh7, addr_hi + 32);
            LDSM_X4_TRANS(bl0, bl1, bl2, bl3, addr_lo);
            LDSM_X4_TRANS(bl4, bl5, bl6, bl7, addr_lo + 32);

            // w_hi*s_hi
            MMA_BF16(acc[0][0], Ah0, bh0, bh1);
            MMA_BF16(acc[0][1], Ah0, bh2, bh3);
            MMA_BF16(acc[0][2], Ah0, bh4, bh5);
            MMA_BF16(acc[0][3], Ah0, bh6, bh7);
            MMA_BF16(acc[1][0], Ah1, bh0, bh1);
            MMA_BF16(acc[1][1], Ah1, bh2, bh3);
            MMA_BF16(acc[1][2], Ah1, bh4, bh5);
            MMA_BF16(acc[1][3], Ah1, bh6, bh7);
            // w_lo*s_hi
            MMA_BF16(acc[0][0], Al0, bh0, bh1);
            MMA_BF16(acc[0][1], Al0, bh2, bh3);
            MMA_BF16(acc[0][2], Al0, bh4, bh5);
            MMA_BF16(acc[0][3], Al0, bh6, bh7);
            MMA_BF16(acc[1][0], Al1, bh0, bh1);
            MMA_BF16(acc[1][1], Al1, bh2, bh3);
            MMA_BF16(acc[1][2], Al1, bh4, bh5);
            MMA_BF16(acc[1][3], Al1, bh6, bh7);
            // w_hi*s_lo
            MMA_BF16(acc[0][0], Ah0, bl0, bl1);
            MMA_BF16(acc[0][1], Ah0, bl2, bl3);
            MMA_BF16(acc[0][2], Ah0, bl4, bl5);
            MMA_BF16(acc[0][3], Ah0, bl6, bl7);
            MMA_BF16(acc[1][0], Ah1, bl0, bl1);
            MMA_BF16(acc[1][1], Ah1, bl2, bl3);
            MMA_BF16(acc[1][2], Ah1, bl4, bl5);
            MMA_BF16(acc[1][3], Ah1, bl6, bl7);

            // consume gathered values -> next buffer
            if (doG) {
#pragma unroll
                for (int q = 0; q < 4; q++) {
                    float s = gv[q][0] * mn.w00 + gv[q][1] * mn.w01
                            + gv[q][2] * mn.w10 + gv[q][3] * mn.w11;
                    bsplit_store(nxtB, cgrp * 32 + ks8 * 4 + q, p, s);
                }
            }
        }
        __syncthreads();
    }

    // ---- Epilogue: D fragment -> gmem with bias ----
#pragma unroll
    for (int f = 0; f < 2; f++) {
        int oo = wm * 32 + f * 16 + g;
        float bd0 = b_def[oo];
        float bd1 = b_def[oo + 8];
        float* orow0 = out + (((size_t)b * On + oo) * Hn + h) * Wn;
        float* orow1 = orow0 + (size_t)8 * HW;
#pragma unroll
        for (int nf = 0; nf < 4; nf++) {
            int pp = wn * 32 + nf * 8 + 2 * tg;
            float2 v0 = { acc[f][nf][0] + bd0, acc[f][nf][1] + bd0 };
            float2 v1 = { acc[f][nf][2] + bd1, acc[f][nf][3] + bd1 };
            *(float2*)(orow0 + pp) = v0;
            *(float2*)(orow1 + pp) = v1;
        }
    }
}

// ---------------------------------------------------------------------------
extern "C" void kernel_launch(void* const* d_in, const int* in_sizes, int n_in,
                              void* d_out, int out_size) {
    const float* x     = (const float*)d_in[0];
    const float* w_off = (const float*)d_in[1];
    const float* b_off = (const float*)d_in[2];
    const float* w_def = (const float*)d_in[3];
    const float* b_def = (const float*)d_in[4];
    float* out = (float*)d_out;

    cudaFuncSetAttribute(main_kernel, cudaFuncAttributeMaxDynamicSharedMemorySize, SM_TOT);

    off_kernel<<<512, 256>>>(x, w_off, b_off, w_def);
    main_kernel<<<Bn * Hn, 256, SM_TOT>>>(x, b_def, out);
}

// round 9
// speedup vs baseline: 3.8366x; 1.1102x over previous
#include <cuda_runtime.h>
#include <cuda_fp16.h>
#include <cstdint>

#define KK9 9
#define NJ  18
#define Bn  8
#define Cn  128
#define Hn  64
#define Wn  64
#define On  128
#define HW  (Hn * Wn)
#define NCHUNK 4
#define BROWB 144                // bytes per B row (64 p * 2B + 16 pad)
#define BROWS 72                 // ushorts per B row
#define SMB_BYTES (128 * BROWB)          // 18432 per buffer (single s_hi plane)
#define SMB_HALF_SHORTS (SMB_BYTES / 2)  // shorts per buffer
#define SM_TOT (2 * SMB_BYTES)           // 36864 B double-buffered

// ---------------- scratch (no allocations allowed) ---------------------------
__device__ float g_off_part[NCHUNK * Bn * NJ * Hn * Wn];
// A fragments: [kk][ks8(8)][reg(2: wh,wl)][mtile(8)][lane(32)] -> uint4 (fp16)
__device__ uint4 g_wAfrag[KK9 * 8 * 2 * 8 * 32];

// ---------------- helpers -----------------------------------------------------
typedef unsigned long long u64t;
__device__ __forceinline__ u64t pack2(float a, float b) {
    u64t r; asm("mov.b64 %0, {%1, %2};" : "=l"(r) : "f"(a), "f"(b)); return r;
}
__device__ __forceinline__ u64t ffma2(u64t a, u64t b, u64t c) {
    u64t d; asm("fma.rn.f32x2 %0, %1, %2, %3;" : "=l"(d) : "l"(a), "l"(b), "l"(c)); return d;
}
__device__ __forceinline__ void unpack2(u64t v, float& lo, float& hi) {
    asm("mov.b64 {%0, %1}, %2;" : "=f"(lo), "=f"(hi) : "l"(v));
}
__device__ __forceinline__ uint32_t smem_u32(const void* p) {
    uint32_t a;
    asm("{ .reg .u64 t; cvta.to.shared.u64 t, %1; cvt.u32.u64 %0, t; }" : "=r"(a) : "l"(p));
    return a;
}
// fp16 weight split: reg 0 = wh = RN(w), reg 1 = wl = RN(w - wh)
__device__ __forceinline__ unsigned short aval2(const float* w_def, int kk, int m, int c, int reg) {
    float w = w_def[(m * Cn + c) * KK9 + kk];
    __half hi = __float2half_rn(w);
    if (reg) {
        __half lo = __float2half_rn(w - __half2float(hi));
        return __half_as_ushort(lo);
    }
    return __half_as_ushort(hi);
}
__device__ __forceinline__ uint32_t apack2(const float* w_def, int kk, int m, int c, int reg) {
    uint32_t lo = aval2(w_def, kk, m, c, reg);
    uint32_t hi = aval2(w_def, kk, m, c + 1, reg);
    return lo | (hi << 16);
}

#define MMA_F16(d, a, b0r, b1r)                                                      \
    asm volatile("mma.sync.aligned.m16n8k16.row.col.f32.f16.f16.f32 "                \
                 "{%0,%1,%2,%3}, {%4,%5,%6,%7}, {%8,%9}, {%0,%1,%2,%3};"             \
                 : "+f"((d)[0]), "+f"((d)[1]), "+f"((d)[2]), "+f"((d)[3])            \
                 : "r"((a).x), "r"((a).y), "r"((a).z), "r"((a).w), "r"(b0r), "r"(b1r))

#define LDSM_X4_TRANS(r0, r1, r2, r3, addr)                                          \
    asm volatile("ldmatrix.sync.aligned.m8n8.x4.trans.shared.b16 {%0,%1,%2,%3}, [%4];" \
                 : "=r"(r0), "=r"(r1), "=r"(r2), "=r"(r3) : "r"(addr))

// sampling metadata recomputed per (p, kk)
struct Meta {
    float w00, w01, w10, w11;
    int   o00, o01, o10, o11;
    bool  v00, v01, v10, v11;
};
__device__ __forceinline__ Meta make_meta(int b, int h, int p, int kk) {
    const size_t CS = (size_t)Bn * NJ * Hn * Wn;
    int ky = kk / 3, kx = kk % 3;
    size_t by = ((size_t)(b * NJ + 2 * kk) * Hn + h) * Wn + p;
    size_t bx = by + (size_t)HW;
    float offy = g_off_part[by] + g_off_part[CS + by]
               + g_off_part[2 * CS + by] + g_off_part[3 * CS + by];
    float offx = g_off_part[bx] + g_off_part[CS + bx]
               + g_off_part[2 * CS + bx] + g_off_part[3 * CS + bx];
    float py = (float)(h - 1 + ky) + offy;
    float px = (float)(p - 1 + kx) + offx;
    float fy = floorf(py), fx = floorf(px);
    int iy0 = (int)fy, ix0 = (int)fx;
    float wy = py - fy, wx = px - fx;
    Meta m;
    m.w00 = (1.f - wy) * (1.f - wx);
    m.w01 = (1.f - wy) * wx;
    m.w10 = wy * (1.f - wx);
    m.w11 = wy * wx;
    int iy1 = iy0 + 1, ix1 = ix0 + 1;
    bool vy0 = (iy0 >= 0) & (iy0 < Hn), vy1 = (iy1 >= 0) & (iy1 < Hn);
    bool vx0 = (ix0 >= 0) & (ix0 < Wn), vx1 = (ix1 >= 0) & (ix1 < Wn);
    m.v00 = vy0 & vx0; m.v01 = vy0 & vx1; m.v10 = vy1 & vx0; m.v11 = vy1 & vx1;
    m.o00 = iy0 * Wn + ix0; m.o01 = iy0 * Wn + ix1;
    m.o10 = iy1 * Wn + ix0; m.o11 = iy1 * Wn + ix1;
    return m;
}
// single fp16 store at row c
__device__ __forceinline__ void bstore(unsigned short* dst, int c, int p, float s) {
    dst[c * BROWS + p] = __half_as_ushort(__float2half_rn(s));
}

// ---------------------------------------------------------------------------
// Kernel 1: offset conv partials (+ fused A-fragment prep)
// ---------------------------------------------------------------------------
__global__ __launch_bounds__(256) void off_kernel(const float* __restrict__ x,
                                                  const float* __restrict__ w_off,
                                                  const float* __restrict__ b_off,
                                                  const float* __restrict__ w_def) {
    {
        int gt = blockIdx.x * 256 + threadIdx.x;
        for (int it = gt; it < KK9 * 8 * 2 * 8 * 32; it += 512 * 256) {
            int lane = it & 31;
            int mt   = (it >> 5) & 7;
            int reg  = (it >> 8) & 1;
            int ks8  = (it >> 9) & 7;
            int kk   = it >> 12;
            int g  = lane >> 2, tg = lane & 3;
            int cb = ks8 * 16 + 2 * tg;
            int m  = mt * 16 + g;
            uint4 v;
            v.x = apack2(w_def, kk, m,     cb,     reg);
            v.y = apack2(w_def, kk, m + 8, cb,     reg);
            v.z = apack2(w_def, kk, m,     cb + 8, reg);
            v.w = apack2(w_def, kk, m + 8, cb + 8, reg);
            g_wAfrag[it] = v;
        }
    }

    __shared__ u64t wch2[32 * KK9 * 10];

    int chunk = blockIdx.x >> 7;
    int pixblk = blockIdx.x & 127;
    int cc = chunk * 32;

    int pix = pixblk * 256 + threadIdx.x;
    int w = pix & 63;
    int h = (pix >> 6) & 63;
    int b = pix >> 12;

    for (int i = threadIdx.x; i < 32 * KK9 * 9; i += 256) {
        int q  = i % 9;
        int jp = (i / 9) % KK9;
        int cl = i / (9 * KK9);
        float lo = w_off[((2 * jp)     * Cn + cc + cl) * 9 + q];
        float hi = w_off[((2 * jp + 1) * Cn + cc + cl) * 9 + q];
        wch2[(cl * KK9 + jp) * 10 + q] = pack2(lo, hi);
    }
    __syncthreads();

    u64t acc2[KK9];
#pragma unroll
    for (int jp = 0; jp < KK9; jp++)
        acc2[jp] = (chunk == 0) ? pack2(b_off[2 * jp], b_off[2 * jp + 1]) : 0ULL;

    for (int cl = 0; cl < 32; cl++) {
        const float* xb = x + ((b * Cn + cc + cl) * Hn) * Wn;
        u64t x2[9];
#pragma unroll
        for (int ky = 0; ky < 3; ky++)
#pragma unroll
            for (int kx = 0; kx < 3; kx++) {
                int y = h - 1 + ky, xx = w - 1 + kx;
                bool v = (y >= 0) & (y < Hn) & (xx >= 0) & (xx < Wn);
                float xv = v ? xb[y * Wn + xx] : 0.0f;
                x2[ky * 3 + kx] = pack2(xv, xv);
            }
#pragma unroll
        for (int jp = 0; jp < KK9; jp++) {
            const u64t* wp = &wch2[(cl * KK9 + jp) * 10];
            ulonglong2 w01 = *(const ulonglong2*)(wp);
            ulonglong2 w23 = *(const ulonglong2*)(wp + 2);
            ulonglong2 w45 = *(const ulonglong2*)(wp + 4);
            ulonglong2 w67 = *(const ulonglong2*)(wp + 6);
            u64t       w8  = wp[8];
            u64t a = acc2[jp];
            a = ffma2(w01.x, x2[0], a);
            a = ffma2(w01.y, x2[1], a);
            a = ffma2(w23.x, x2[2], a);
            a = ffma2(w23.y, x2[3], a);
            a = ffma2(w45.x, x2[4], a);
            a = ffma2(w45.y, x2[5], a);
            a = ffma2(w67.x, x2[6], a);
            a = ffma2(w67.y, x2[7], a);
            a = ffma2(w8,    x2[8], a);
            acc2[jp] = a;
        }
    }

    float* op = g_off_part + (size_t)chunk * Bn * NJ * Hn * Wn;
#pragma unroll
    for (int jp = 0; jp < KK9; jp++) {
        float lo, hi;
        unpack2(acc2[jp], lo, hi);
        op[((b * NJ + 2 * jp)     * Hn + h) * Wn + w] = lo;
        op[((b * NJ + 2 * jp + 1) * Hn + h) * Wn + w] = hi;
    }
}

// ---------------------------------------------------------------------------
// Kernel 2: pipelined gather + mma.sync fp16 2-term split GEMM.
// B buffer: 128 rows (s fp16). Per 16-channel step: load A_wh/A_wl/B once,
// issue wh*s and wl*s MMAs from registers.
// ---------------------------------------------------------------------------
__global__ __launch_bounds__(256, 2) void main_kernel(const float* __restrict__ x,
                                                      const float* __restrict__ b_def,
                                                      float* __restrict__ out) {
    extern __shared__ char sm[];
    unsigned short* sB = (unsigned short*)sm;
    uint32_t smB = smem_u32(sm);

    int tid  = threadIdx.x;
    int wid  = tid >> 5;
    int lane = tid & 31;
    int b = blockIdx.x >> 6;
    int h = blockIdx.x & 63;

    // warp tiling: 4m x 2n
    int wm = wid >> 1;
    int wn = wid & 1;
    int g  = lane >> 2, tg = lane & 3;

    float acc[2][4][4];
#pragma unroll
    for (int f = 0; f < 2; f++)
#pragma unroll
        for (int nf = 0; nf < 4; nf++)
#pragma unroll
            for (int q = 0; q < 4; q++) acc[f][nf][q] = 0.0f;

    // gather mapping: thread = (pixel p, 32-channel group)
    int p    = tid & 63;
    int cgrp = tid >> 6;
    const float* xb0 = x + (size_t)(b * Cn + cgrp * 32) * HW;

    // ldmatrix per-lane byte offset within a buffer
    int lr    = lane & 7;
    int khalf = ((lane >> 3) & 1) * 8;
    int pgrp  = lane >> 4;
    uint32_t browbase = (uint32_t)((khalf + lr) * BROWB + (wn * 32 + pgrp * 8) * 2);

    // ---- prologue: gather kk=0 into buffer 0 ----
    {
        Meta m0 = make_meta(b, h, p, 0);
#pragma unroll 8
        for (int ci = 0; ci < 32; ci++) {
            const float* xc = xb0 + ci * HW;
            float a00 = m0.v00 ? xc[m0.o00] : 0.0f;
            float a01 = m0.v01 ? xc[m0.o01] : 0.0f;
            float a10 = m0.v10 ? xc[m0.o10] : 0.0f;
            float a11 = m0.v11 ? xc[m0.o11] : 0.0f;
            float s = a00 * m0.w00 + a01 * m0.w01 + a10 * m0.w10 + a11 * m0.w11;
            bstore(sB, cgrp * 32 + ci, p, s);
        }
    }
    __syncthreads();

    // ---- main pipelined loop over kk ----
    for (int kk = 0; kk < KK9; kk++) {
        uint32_t curOff = (uint32_t)((kk & 1) * SMB_BYTES);
        unsigned short* nxtB = sB + ((kk + 1) & 1) * SMB_HALF_SHORTS;
        bool doG = (kk < KK9 - 1);
        Meta mn;
        if (doG) mn = make_meta(b, h, p, kk + 1);
        const uint4* ap = g_wAfrag + (size_t)kk * (8 * 2 * 8 * 32);

        for (int ks8 = 0; ks8 < 8; ks8++) {
            // issue next-kk gather loads (latency overlaps the MMAs below)
            float gv[4][4];
            if (doG) {
#pragma unroll
                for (int q = 0; q < 4; q++) {
                    const float* xc = xb0 + (ks8 * 4 + q) * HW;
                    gv[q][0] = mn.v00 ? xc[mn.o00] : 0.0f;
                    gv[q][1] = mn.v01 ? xc[mn.o01] : 0.0f;
                    gv[q][2] = mn.v10 ? xc[mn.o10] : 0.0f;
                    gv[q][3] = mn.v11 ? xc[mn.o11] : 0.0f;
                }
            }

            // A fragments: wh + wl (each 2 m-frags)
            const uint4* a_hi = ap + ((size_t)(ks8 * 2)     * 8 + wm * 2) * 32 + lane;
            const uint4* a_lo = ap + ((size_t)(ks8 * 2 + 1) * 8 + wm * 2) * 32 + lane;
            uint4 Ah0 = a_hi[0], Ah1 = a_hi[32];
            uint4 Al0 = a_lo[0], Al1 = a_lo[32];

            // B fragments: single s plane
            uint32_t addr = smB + curOff + browbase + (uint32_t)(ks8 * 16 * BROWB);
            uint32_t b0, b1, b2, b3, b4, b5, b6, b7;
            LDSM_X4_TRANS(b0, b1, b2, b3, addr);
            LDSM_X4_TRANS(b4, b5, b6, b7, addr + 32);

            // wh*s
            MMA_F16(acc[0][0], Ah0, b0, b1);
            MMA_F16(acc[0][1], Ah0, b2, b3);
            MMA_F16(acc[0][2], Ah0, b4, b5);
            MMA_F16(acc[0][3], Ah0, b6, b7);
            MMA_F16(acc[1][0], Ah1, b0, b1);
            MMA_F16(acc[1][1], Ah1, b2, b3);
            MMA_F16(acc[1][2], Ah1, b4, b5);
            MMA_F16(acc[1][3], Ah1, b6, b7);
            // wl*s
            MMA_F16(acc[0][0], Al0, b0, b1);
            MMA_F16(acc[0][1], Al0, b2, b3);
            MMA_F16(acc[0][2], Al0, b4, b5);
            MMA_F16(acc[0][3], Al0, b6, b7);
            MMA_F16(acc[1][0], Al1, b0, b1);
            MMA_F16(acc[1][1], Al1, b2, b3);
            MMA_F16(acc[1][2], Al1, b4, b5);
            MMA_F16(acc[1][3], Al1, b6, b7);

            // consume gathered values -> next buffer
            if (doG) {
#pragma unroll
                for (int q = 0; q < 4; q++) {
                    float s = gv[q][0] * mn.w00 + gv[q][1] * mn.w01
                            + gv[q][2] * mn.w10 + gv[q][3] * mn.w11;
                    bstore(nxtB, cgrp * 32 + ks8 * 4 + q, p, s);
                }
            }
        }
        __syncthreads();
    }

    // ---- Epilogue: D fragment -> gmem with bias ----
#pragma unroll
    for (int f = 0; f < 2; f++) {
        int oo = wm * 32 + f * 16 + g;
        float bd0 = b_def[oo];
        float bd1 = b_def[oo + 8];
        float* orow0 = out + (((size_t)b * On + oo) * Hn + h) * Wn;
        float* orow1 = orow0 + (size_t)8 * HW;
#pragma unroll
        for (int nf = 0; nf < 4; nf++) {
            int pp = wn * 32 + nf * 8 + 2 * tg;
            float2 v0 = { acc[f][nf][0] + bd0, acc[f][nf][1] + bd0 };
            float2 v1 = { acc[f][nf][2] + bd1, acc[f][nf][3] + bd1 };
            *(float2*)(orow0 + pp) = v0;
            *(float2*)(orow1 + pp) = v1;
        }
    }
}

// ---------------------------------------------------------------------------
extern "C" void kernel_launch(void* const* d_in, const int* in_sizes, int n_in,
                              void* d_out, int out_size) {
    const float* x     = (const float*)d_in[0];
    const float* w_off = (const float*)d_in[1];
    const float* b_off = (const float*)d_in[2];
    const float* w_def = (const float*)d_in[3];
    const float* b_def = (const float*)d_in[4];
    float* out = (float*)d_out;

    cudaFuncSetAttribute(main_kernel, cudaFuncAttributeMaxDynamicSharedMemorySize, SM_TOT);

    off_kernel<<<512, 256>>>(x, w_off, b_off, w_def);
    main_kernel<<<Bn * Hn, 256, SM_TOT>>>(x, b_def, out);
}